// round 1
// baseline (speedup 1.0000x reference)
#include <cuda_runtime.h>

#define CC 512
#define CQn 64
#define HH 128
#define WW 128
#define BB 4
#define CO 640            // CQ + CQ + C
#define NP (HH*WW)        // 16384 pixels per channel plane

// ---------------- scratch (static device arrays; no allocation) ----------------
__device__ float g_qkv[(size_t)BB*CO*NP];      // (b, o, p) o: 0..63=q, 64..127=k, 128..639=v
__device__ float g_ch [(size_t)BB*CC*HH*WW];   // horizontal result, same layout as output
__device__ float g_cv [(size_t)BB*WW*HH*CC];   // vertical result, ((b*W+w)*H + h)*C + c
__device__ float g_Wall[CO*CC];
__device__ float g_ball[CO];

// ---------------- kernel 1: pack weights ----------------
__global__ void pack_kernel(const float* __restrict__ Wq, const float* __restrict__ bq,
                            const float* __restrict__ Wk, const float* __restrict__ bk,
                            const float* __restrict__ Wv, const float* __restrict__ bv) {
    int idx = blockIdx.x * blockDim.x + threadIdx.x;
    if (idx < CO * CC) {
        int o = idx / CC, c = idx % CC;
        float v;
        if (o < CQn)            v = Wq[o * CC + c];
        else if (o < 2 * CQn)   v = Wk[(o - CQn) * CC + c];
        else                    v = Wv[(o - 2 * CQn) * CC + c];
        g_Wall[idx] = v;
    }
    if (idx < CO) {
        g_ball[idx] = (idx < CQn) ? bq[idx] : (idx < 2 * CQn) ? bk[idx - CQn] : bv[idx - 2 * CQn];
    }
}

// ---------------- kernel 2: QKV projection GEMM ----------------
// C[o][p] = sum_c Wall[o][c] * x[b][c][p] + ball[o]
// grid: (5 Mtiles, 128 Ntiles, 4 batches), 256 threads, 128x128x8 tiling, 8x8 micro-tile
__global__ __launch_bounds__(256) void qkv_gemm(const float* __restrict__ x) {
    int m0 = blockIdx.x * 128;
    int n0 = blockIdx.y * 128;
    int b  = blockIdx.z;

    const float* A = g_Wall;                         // 640x512 row-major
    const float* B = x + (size_t)b * CC * NP;        // 512x16384 row-major
    float*       Cp = g_qkv + (size_t)b * CO * NP;

    __shared__ float As[8][128];
    __shared__ float Bs[8][128];

    int tid = threadIdx.x;
    int tx = tid % 16, ty = tid / 16;

    int arow = tid / 2, acol = (tid % 2) * 4;        // A tile 128x8
    int brow = tid / 32, bcol = (tid % 32) * 4;      // B tile 8x128

    float acc[8][8];
    #pragma unroll
    for (int u = 0; u < 8; u++)
        #pragma unroll
        for (int v = 0; v < 8; v++) acc[u][v] = 0.f;

    for (int k0 = 0; k0 < CC; k0 += 8) {
        float4 a4 = *reinterpret_cast<const float4*>(&A[(m0 + arow) * CC + k0 + acol]);
        As[acol + 0][arow] = a4.x;
        As[acol + 1][arow] = a4.y;
        As[acol + 2][arow] = a4.z;
        As[acol + 3][arow] = a4.w;
        *reinterpret_cast<float4*>(&Bs[brow][bcol]) =
            *reinterpret_cast<const float4*>(&B[(size_t)(k0 + brow) * NP + n0 + bcol]);
        __syncthreads();
        #pragma unroll
        for (int k = 0; k < 8; k++) {
            float af[8], bf[8];
            *reinterpret_cast<float4*>(&af[0]) = *reinterpret_cast<const float4*>(&As[k][ty * 8]);
            *reinterpret_cast<float4*>(&af[4]) = *reinterpret_cast<const float4*>(&As[k][ty * 8 + 4]);
            *reinterpret_cast<float4*>(&bf[0]) = *reinterpret_cast<const float4*>(&Bs[k][tx * 8]);
            *reinterpret_cast<float4*>(&bf[4]) = *reinterpret_cast<const float4*>(&Bs[k][tx * 8 + 4]);
            #pragma unroll
            for (int u = 0; u < 8; u++)
                #pragma unroll
                for (int v = 0; v < 8; v++) acc[u][v] += af[u] * bf[v];
        }
        __syncthreads();
    }

    #pragma unroll
    for (int u = 0; u < 8; u++) {
        int m = m0 + ty * 8 + u;
        float bias = g_ball[m];
        #pragma unroll
        for (int v = 0; v < 8; v += 4) {
            float4 o;
            o.x = acc[u][v + 0] + bias;
            o.y = acc[u][v + 1] + bias;
            o.z = acc[u][v + 2] + bias;
            o.w = acc[u][v + 3] + bias;
            *reinterpret_cast<float4*>(&Cp[(size_t)m * NP + n0 + tx * 8 + v]) = o;
        }
    }
}

// ---------------- kernel 3: horizontal (row) attention ----------------
// For row (b,h):
//   energy[i, 64t+c] = sum_a q[b,a,h,i] * k[b,c,h,2a+t]     (faithful .view quirk)
//   A = softmax(energy);  ch[b,m,h,i] = sum_j A[i,j] * v[b,m,h,j]
__global__ __launch_bounds__(256) void h_attn() {
    int bh = blockIdx.x;
    int b = bh >> 7, h = bh & 127;
    extern __shared__ float sm[];
    float* qs = sm;                 // [64][128]  q[a][i]           8192
    float* ks = sm + 8192;          // [128][68]  k[w][c] padded    8704
    float* es = sm + 16896;         // [128][129] energy padded     16512
    float* vs = sm;                 // reused: V chunk [128][68] / out staging
    int tid = threadIdx.x;

    const float* qbase = g_qkv + (size_t)b * CO * NP + h * WW;
    for (int idx = tid; idx < CQn * WW; idx += 256) {
        int a = idx >> 7, i = idx & 127;
        qs[idx] = qbase[a * NP + i];
    }
    const float* kbase = qbase + CQn * NP;
    for (int idx = tid; idx < CQn * WW; idx += 256) {
        int c = idx >> 7, w = idx & 127;
        ks[w * 68 + c] = kbase[c * NP + w];
    }
    __syncthreads();

    // energy: 4 j's per thread-iter
    for (int g = tid; g < (WW * WW) / 4; g += 256) {
        int i = g >> 5;
        int j0 = (g & 31) * 4;
        int t = j0 >> 6;
        int c0 = j0 & 63;
        float e0 = 0.f, e1 = 0.f, e2 = 0.f, e3 = 0.f;
        #pragma unroll
        for (int a = 0; a < CQn; a++) {
            float qv = qs[a * 128 + i];
            float4 kk = *reinterpret_cast<const float4*>(&ks[(2 * a + t) * 68 + c0]);
            e0 += qv * kk.x; e1 += qv * kk.y; e2 += qv * kk.z; e3 += qv * kk.w;
        }
        es[i * 129 + j0 + 0] = e0;
        es[i * 129 + j0 + 1] = e1;
        es[i * 129 + j0 + 2] = e2;
        es[i * 129 + j0 + 3] = e3;
    }
    __syncthreads();

    // softmax, one row per thread
    if (tid < 128) {
        float* row = es + tid * 129;
        float mx = -1e30f;
        for (int j = 0; j < 128; j++) mx = fmaxf(mx, row[j]);
        float s = 0.f;
        for (int j = 0; j < 128; j++) { float e = __expf(row[j] - mx); row[j] = e; s += e; }
        float inv = 1.f / s;
        for (int j = 0; j < 128; j++) row[j] *= inv;
    }
    __syncthreads();

    // A @ V, chunks of 64 channels
    int mx8 = tid & 7;    // m group: m = mx8*8 .. +7
    int iy  = tid >> 3;   // i group: i = iy*4 .. +3
    const float* vbase = qbase + 2 * CQn * NP;
    float* chb = g_ch + (size_t)((b * CC) * HH + h) * WW;
    for (int mc = 0; mc < CC; mc += 64) {
        for (int idx = tid; idx < 64 * 128; idx += 256) {
            int ml = idx >> 7, j = idx & 127;
            vs[j * 68 + ml] = vbase[(mc + ml) * NP + j];
        }
        __syncthreads();
        float acc[4][8];
        #pragma unroll
        for (int ii = 0; ii < 4; ii++)
            #pragma unroll
            for (int mm = 0; mm < 8; mm++) acc[ii][mm] = 0.f;
        for (int j = 0; j < 128; j++) {
            float4 v0 = *reinterpret_cast<const float4*>(&vs[j * 68 + mx8 * 8]);
            float4 v1 = *reinterpret_cast<const float4*>(&vs[j * 68 + mx8 * 8 + 4]);
            #pragma unroll
            for (int ii = 0; ii < 4; ii++) {
                float a = es[(iy * 4 + ii) * 129 + j];
                acc[ii][0] += a * v0.x; acc[ii][1] += a * v0.y;
                acc[ii][2] += a * v0.z; acc[ii][3] += a * v0.w;
                acc[ii][4] += a * v1.x; acc[ii][5] += a * v1.y;
                acc[ii][6] += a * v1.z; acc[ii][7] += a * v1.w;
            }
        }
        __syncthreads();
        // stage (m-major -> coalesced global write over i)
        #pragma unroll
        for (int ii = 0; ii < 4; ii++) {
            int i = iy * 4 + ii;
            #pragma unroll
            for (int mm = 0; mm < 8; mm++)
                vs[(mx8 * 8 + mm) * 128 + i] = acc[ii][mm];
        }
        __syncthreads();
        for (int idx = tid; idx < 64 * 128; idx += 256) {
            int ml = idx >> 7, i = idx & 127;
            chb[(size_t)(mc + ml) * NP + i] = vs[idx];
        }
        __syncthreads();
    }
}

// ---------------- kernel 4: vertical (column) attention ----------------
// For column (b,w):
//   energy[i,j] = sum_a q[b, i/2, 64*(i%2)+a, w] * k[b, a, j, w]
//   A = softmax(energy); cv[(b,w), i, 128t+p] = sum_j A[i,j] * v[b, 4j+t, p, w]
__global__ __launch_bounds__(256) void v_attn() {
    int bw = blockIdx.x;
    int b = bw >> 7, w = bw & 127;
    extern __shared__ float sm[];
    float* qs = sm;                 // [64][128]  q[c][h]           8192
    float* ks = sm + 8192;          // [64][132]  k[a][j] padded    8448
    float* es = sm + 16640;         // [128][129]                   16512
    float* vs = sm;                 // reused chunk [128][68]
    int tid = threadIdx.x;

    const float* qbase = g_qkv + (size_t)b * CO * NP + w;
    for (int idx = tid; idx < CQn * HH; idx += 256) {
        int c = idx >> 7, hh = idx & 127;
        qs[idx] = qbase[c * NP + hh * WW];
    }
    const float* kbase = qbase + CQn * NP;
    for (int idx = tid; idx < CQn * HH; idx += 256) {
        int a = idx >> 7, j = idx & 127;
        ks[a * 132 + j] = kbase[a * NP + j * WW];
    }
    __syncthreads();

    for (int g = tid; g < (HH * HH) / 4; g += 256) {
        int i = g >> 5;
        int j0 = (g & 31) * 4;
        const float* qrow = qs + (i >> 1) * 128 + ((i & 1) << 6);
        float e0 = 0.f, e1 = 0.f, e2 = 0.f, e3 = 0.f;
        #pragma unroll
        for (int a = 0; a < CQn; a++) {
            float qq = qrow[a];
            float4 kk = *reinterpret_cast<const float4*>(&ks[a * 132 + j0]);
            e0 += qq * kk.x; e1 += qq * kk.y; e2 += qq * kk.z; e3 += qq * kk.w;
        }
        es[i * 129 + j0 + 0] = e0;
        es[i * 129 + j0 + 1] = e1;
        es[i * 129 + j0 + 2] = e2;
        es[i * 129 + j0 + 3] = e3;
    }
    __syncthreads();

    if (tid < 128) {
        float* row = es + tid * 129;
        float mx = -1e30f;
        for (int j = 0; j < 128; j++) mx = fmaxf(mx, row[j]);
        float s = 0.f;
        for (int j = 0; j < 128; j++) { float e = __expf(row[j] - mx); row[j] = e; s += e; }
        float inv = 1.f / s;
        for (int j = 0; j < 128; j++) row[j] *= inv;
    }
    __syncthreads();

    int mx8 = tid & 7;
    int iy  = tid >> 3;
    const float* vbase = g_qkv + (size_t)(b * CO + 2 * CQn) * NP + w;
    float* cvrow = g_cv + (size_t)bw * HH * CC;
    for (int cc = 0; cc < 8; cc++) {
        int t = cc >> 1, ph = cc & 1;
        // vs[j][ml] = v[b][4j+t][64*ph+ml][w]
        for (int idx = tid; idx < 64 * 128; idx += 256) {
            int j = idx >> 6, ml = idx & 63;
            vs[j * 68 + ml] = vbase[(size_t)(4 * j + t) * NP + (64 * ph + ml) * WW];
        }
        __syncthreads();
        float acc[4][8];
        #pragma unroll
        for (int ii = 0; ii < 4; ii++)
            #pragma unroll
            for (int mm = 0; mm < 8; mm++) acc[ii][mm] = 0.f;
        for (int j = 0; j < 128; j++) {
            float4 v0 = *reinterpret_cast<const float4*>(&vs[j * 68 + mx8 * 8]);
            float4 v1 = *reinterpret_cast<const float4*>(&vs[j * 68 + mx8 * 8 + 4]);
            #pragma unroll
            for (int ii = 0; ii < 4; ii++) {
                float a = es[(iy * 4 + ii) * 129 + j];
                acc[ii][0] += a * v0.x; acc[ii][1] += a * v0.y;
                acc[ii][2] += a * v0.z; acc[ii][3] += a * v0.w;
                acc[ii][4] += a * v1.x; acc[ii][5] += a * v1.y;
                acc[ii][6] += a * v1.z; acc[ii][7] += a * v1.w;
            }
        }
        // direct contiguous write: m = 128t + 64ph + mx8*8 + {0..7}
        int mbase = 128 * t + 64 * ph + mx8 * 8;
        #pragma unroll
        for (int ii = 0; ii < 4; ii++) {
            int i = iy * 4 + ii;
            float4 o0, o1;
            o0.x = acc[ii][0]; o0.y = acc[ii][1]; o0.z = acc[ii][2]; o0.w = acc[ii][3];
            o1.x = acc[ii][4]; o1.y = acc[ii][5]; o1.z = acc[ii][6]; o1.w = acc[ii][7];
            *reinterpret_cast<float4*>(&cvrow[(size_t)i * CC + mbase])     = o0;
            *reinterpret_cast<float4*>(&cvrow[(size_t)i * CC + mbase + 4]) = o1;
        }
        __syncthreads();
    }
}

// ---------------- kernel 5: combine out = gamma*(ch + cv) + x ----------------
// cv is (b,w,h,c); transpose-tile over (w,c) for each (b,h)
__global__ __launch_bounds__(256) void combine_kernel(const float* __restrict__ x,
                                                      const float* __restrict__ gamma,
                                                      float* __restrict__ out) {
    __shared__ float tb[32][33];
    int w0 = blockIdx.x * 32;
    int c0 = blockIdx.y * 32;
    int bh = blockIdx.z;
    int b = bh >> 7, h = bh & 127;
    int tx = threadIdx.x, ty = threadIdx.y;

    for (int r = ty; r < 32; r += 8) {
        int w = w0 + r;
        tb[r][tx] = g_cv[(size_t)((b * WW + w) * HH + h) * CC + c0 + tx];
    }
    __syncthreads();
    float g = gamma[0];
    for (int r = ty; r < 32; r += 8) {
        int c = c0 + r;
        int w = w0 + tx;
        size_t o = (size_t)((b * CC + c) * HH + h) * WW + w;
        out[o] = g * (g_ch[o] + tb[tx][r]) + x[o];
    }
}

// ---------------- launch ----------------
extern "C" void kernel_launch(void* const* d_in, const int* in_sizes, int n_in,
                              void* d_out, int out_size) {
    const float* x     = (const float*)d_in[0];
    const float* Wq    = (const float*)d_in[1];
    const float* bq    = (const float*)d_in[2];
    const float* Wk    = (const float*)d_in[3];
    const float* bk    = (const float*)d_in[4];
    const float* Wv    = (const float*)d_in[5];
    const float* bv    = (const float*)d_in[6];
    const float* gamma = (const float*)d_in[7];
    float* out = (float*)d_out;

    const int HSMEM = (16896 + 16512) * 4;   // 133632 B
    const int VSMEM = (16640 + 16512) * 4;   // 132608 B
    cudaFuncSetAttribute(h_attn, cudaFuncAttributeMaxDynamicSharedMemorySize, HSMEM);
    cudaFuncSetAttribute(v_attn, cudaFuncAttributeMaxDynamicSharedMemorySize, VSMEM);

    pack_kernel<<<(CO * CC + 255) / 256, 256>>>(Wq, bq, Wk, bk, Wv, bv);
    qkv_gemm<<<dim3(5, 128, 4), 256>>>(x);
    h_attn<<<BB * HH, 256, HSMEM>>>();
    v_attn<<<BB * WW, 256, VSMEM>>>();
    combine_kernel<<<dim3(WW / 32, CC / 32, BB * HH), dim3(32, 8, 1)>>>(x, gamma, out);
}

// round 2
// speedup vs baseline: 2.0612x; 2.0612x over previous
#include <cuda_runtime.h>

#define CC 512
#define CQn 64
#define HH 128
#define WW 128
#define BB 4
#define CO 640            // CQ + CQ + C
#define NP (HH*WW)

// ---------------- scratch ----------------
__device__ float g_qkv [(size_t)BB*CO*NP];     // (b, o, h, w)
__device__ float g_qkvT[(size_t)BB*CO*NP];     // (b, o, w, h)
__device__ float g_ch  [(size_t)BB*CC*HH*WW];  // horizontal result (b,c,h,w)
__device__ float g_cv  [(size_t)BB*WW*HH*CC];  // vertical result ((b*W+w)*H+h)*C + c
__device__ float g_Wall[CO*CC];
__device__ float g_ball[CO];

// ---------------- tf32 helpers ----------------
__device__ __forceinline__ unsigned f2tf(float f) {
    unsigned u; asm("cvt.rna.tf32.f32 %0, %1;" : "=r"(u) : "f"(f)); return u;
}
__device__ __forceinline__ float f2tff(float f) { unsigned u = f2tf(f); return __uint_as_float(u); }

__device__ __forceinline__ void mma_tf32(float c[4], const unsigned a[4], const unsigned b[2]) {
    asm volatile("mma.sync.aligned.m16n8k8.row.col.f32.tf32.tf32.f32 "
        "{%0,%1,%2,%3}, {%4,%5,%6,%7}, {%8,%9}, {%0,%1,%2,%3};"
        : "+f"(c[0]), "+f"(c[1]), "+f"(c[2]), "+f"(c[3])
        : "r"(a[0]), "r"(a[1]), "r"(a[2]), "r"(a[3]), "r"(b[0]), "r"(b[1]));
}

// ---------------- kernel 1: pack weights (pre-rounded to tf32) ----------------
__global__ void pack_kernel(const float* __restrict__ Wq, const float* __restrict__ bq,
                            const float* __restrict__ Wk, const float* __restrict__ bk,
                            const float* __restrict__ Wv, const float* __restrict__ bv) {
    int idx = blockIdx.x * blockDim.x + threadIdx.x;
    if (idx < CO * CC) {
        int o = idx / CC, c = idx % CC;
        float v;
        if (o < CQn)            v = Wq[o * CC + c];
        else if (o < 2 * CQn)   v = Wk[(o - CQn) * CC + c];
        else                    v = Wv[(o - 2 * CQn) * CC + c];
        g_Wall[idx] = f2tff(v);
    }
    if (idx < CO) {
        g_ball[idx] = (idx < CQn) ? bq[idx] : (idx < 2 * CQn) ? bk[idx - CQn] : bv[idx - 2 * CQn];
    }
}

// ---------------- kernel 2: QKV projection, tf32 MMA ----------------
// C[o][p] = sum_c W[o][c]*x[c][p] + bias[o].  Block 128x128, K-tile 16, 8 warps (4x2).
__global__ __launch_bounds__(256) void qkv_gemm(const float* __restrict__ x) {
    __shared__ float As[128 * 20];   // A[m][k], stride 20 (20%32==20 -> 4g+tc? 20*g: bijective set)
    __shared__ float Bs[16 * 136];   // B[k][n], stride 136 (8 mod 32)

    int m0 = blockIdx.x * 128;
    int n0 = blockIdx.y * 128;
    int b  = blockIdx.z;

    const float* A = g_Wall;
    const float* B = x + (size_t)b * CC * NP;
    float*       Cp = g_qkv + (size_t)b * CO * NP;

    int tid = threadIdx.x;
    int wid = tid >> 5, lane = tid & 31;
    int wm = wid >> 1, wn = wid & 1;        // warp tile: rows wm*32, cols wn*64
    int g = lane >> 2, tc = lane & 3;

    const unsigned* Asu = (const unsigned*)As;
    const unsigned* Bsu = (const unsigned*)Bs;

    float acc[2][8][4];
    #pragma unroll
    for (int mf = 0; mf < 2; mf++)
        #pragma unroll
        for (int nf = 0; nf < 8; nf++)
            #pragma unroll
            for (int r = 0; r < 4; r++) acc[mf][nf][r] = 0.f;

    int arow = tid >> 2, acol = (tid & 3) * 4;      // A: 128x16, two 64-row halves
    int brow = tid >> 5, bcol = lane * 4;           // B: 16x128, two 8-row halves

    for (int k0 = 0; k0 < CC; k0 += 16) {
        __syncthreads();
        #pragma unroll
        for (int h = 0; h < 2; h++) {
            float4 a4 = *reinterpret_cast<const float4*>(&A[(size_t)(m0 + arow + h * 64) * CC + k0 + acol]);
            // W already tf32-rounded in pack
            As[(arow + h * 64) * 20 + acol + 0] = a4.x;
            As[(arow + h * 64) * 20 + acol + 1] = a4.y;
            As[(arow + h * 64) * 20 + acol + 2] = a4.z;
            As[(arow + h * 64) * 20 + acol + 3] = a4.w;
            float4 b4 = *reinterpret_cast<const float4*>(&B[(size_t)(k0 + brow + h * 8) * NP + n0 + bcol]);
            Bs[(brow + h * 8) * 136 + bcol + 0] = f2tff(b4.x);
            Bs[(brow + h * 8) * 136 + bcol + 1] = f2tff(b4.y);
            Bs[(brow + h * 8) * 136 + bcol + 2] = f2tff(b4.z);
            Bs[(brow + h * 8) * 136 + bcol + 3] = f2tff(b4.w);
        }
        __syncthreads();

        #pragma unroll
        for (int ks = 0; ks < 16; ks += 8) {
            unsigned af[2][4];
            #pragma unroll
            for (int mf = 0; mf < 2; mf++) {
                int r0 = wm * 32 + mf * 16 + g;
                af[mf][0] = Asu[(r0    ) * 20 + ks + tc];
                af[mf][1] = Asu[(r0 + 8) * 20 + ks + tc];
                af[mf][2] = Asu[(r0    ) * 20 + ks + tc + 4];
                af[mf][3] = Asu[(r0 + 8) * 20 + ks + tc + 4];
            }
            unsigned bf[8][2];
            #pragma unroll
            for (int nf = 0; nf < 8; nf++) {
                int nn = wn * 64 + nf * 8 + g;
                bf[nf][0] = Bsu[(ks + tc    ) * 136 + nn];
                bf[nf][1] = Bsu[(ks + tc + 4) * 136 + nn];
            }
            #pragma unroll
            for (int mf = 0; mf < 2; mf++)
                #pragma unroll
                for (int nf = 0; nf < 8; nf++)
                    mma_tf32(acc[mf][nf], af[mf], bf[nf]);
        }
    }

    #pragma unroll
    for (int mf = 0; mf < 2; mf++) {
        int i0 = m0 + wm * 32 + mf * 16 + g;
        float bv0 = g_ball[i0], bv1 = g_ball[i0 + 8];
        #pragma unroll
        for (int nf = 0; nf < 8; nf++) {
            int j = n0 + wn * 64 + nf * 8 + 2 * tc;
            float2 o0, o1;
            o0.x = acc[mf][nf][0] + bv0; o0.y = acc[mf][nf][1] + bv0;
            o1.x = acc[mf][nf][2] + bv1; o1.y = acc[mf][nf][3] + bv1;
            *reinterpret_cast<float2*>(&Cp[(size_t)i0 * NP + j])       = o0;
            *reinterpret_cast<float2*>(&Cp[(size_t)(i0 + 8) * NP + j]) = o1;
        }
    }
}

// ---------------- kernel 3: per-plane (H,W) transpose -> g_qkvT ----------------
__global__ __launch_bounds__(256) void transpose_hw() {
    __shared__ float t[32][33];
    int plane = blockIdx.z;
    const float* src = g_qkv + (size_t)plane * NP;
    float*       dst = g_qkvT + (size_t)plane * NP;
    int w0 = blockIdx.x * 32, h0 = blockIdx.y * 32;
    int tx = threadIdx.x, ty = threadIdx.y;
    #pragma unroll
    for (int r = 0; r < 32; r += 8)
        t[ty + r][tx] = src[(size_t)(h0 + ty + r) * WW + w0 + tx];
    __syncthreads();
    #pragma unroll
    for (int r = 0; r < 32; r += 8)
        dst[(size_t)(w0 + ty + r) * HH + h0 + tx] = t[tx][ty + r];
}

// ---------------- kernel 4: horizontal attention, tf32 MMA ----------------
// energy[i, 64t+c] = sum_a q[a][i] * k[c][2a+t];  A=softmax;  ch[m][i] = sum_j A[i,j] v[m][j]
__global__ __launch_bounds__(256) void h_attn() {
    int bh = blockIdx.x;
    int b = bh >> 7, h = bh & 127;
    extern __shared__ float sm[];
    float* es = sm;                       // [128][132]
    float* r2 = sm + 128 * 132;           // 17408 floats
    float* qs = r2;                       // [64][136]  A-layout: qs[a*136 + i]
    float* kb = r2 + 64 * 136;            // [128][68]  B-layout: kb[j*68 + a]
    float* vb = r2;                       // reuse: [128][132] V chunk (B: vb[m*132+j])
    float* st = r2;                       // reuse: [128][132] staging st[m*132+i]

    int tid = threadIdx.x;
    int wid = tid >> 5, lane = tid & 31;
    int wm = wid >> 1, wn = wid & 1;
    int g = lane >> 2, tc = lane & 3;
    int ib = wm * 32, jb = wn * 64;

    const float* qbase = g_qkv + (size_t)b * CO * NP + h * WW;
    const float* kbase = qbase + (size_t)CQn * NP;

    for (int idx = tid; idx < CQn * WW; idx += 256) {
        int a = idx >> 7, i = idx & 127;
        qs[a * 136 + i] = f2tff(qbase[(size_t)a * NP + i]);
    }
    for (int idx = tid; idx < CQn * WW; idx += 256) {
        int c = idx >> 7, w = idx & 127;
        kb[(((w & 1) << 6) + c) * 68 + (w >> 1)] = f2tff(kbase[(size_t)c * NP + w]);
    }
    __syncthreads();

    // energy MMA: M=i(128), N=j(128), K=a(64)
    {
        const unsigned* qsu = (const unsigned*)qs;
        const unsigned* kbu = (const unsigned*)kb;
        float acc[2][8][4];
        #pragma unroll
        for (int mf = 0; mf < 2; mf++)
            #pragma unroll
            for (int nf = 0; nf < 8; nf++)
                #pragma unroll
                for (int r = 0; r < 4; r++) acc[mf][nf][r] = 0.f;

        for (int a0 = 0; a0 < 64; a0 += 8) {
            unsigned af[2][4];
            #pragma unroll
            for (int mf = 0; mf < 2; mf++) {
                int r0 = ib + mf * 16 + g;
                af[mf][0] = qsu[(a0 + tc    ) * 136 + r0];
                af[mf][1] = qsu[(a0 + tc    ) * 136 + r0 + 8];
                af[mf][2] = qsu[(a0 + tc + 4) * 136 + r0];
                af[mf][3] = qsu[(a0 + tc + 4) * 136 + r0 + 8];
            }
            unsigned bf[8][2];
            #pragma unroll
            for (int nf = 0; nf < 8; nf++) {
                int j = jb + nf * 8 + g;
                bf[nf][0] = kbu[j * 68 + a0 + tc];
                bf[nf][1] = kbu[j * 68 + a0 + tc + 4];
            }
            #pragma unroll
            for (int mf = 0; mf < 2; mf++)
                #pragma unroll
                for (int nf = 0; nf < 8; nf++)
                    mma_tf32(acc[mf][nf], af[mf], bf[nf]);
        }
        #pragma unroll
        for (int mf = 0; mf < 2; mf++) {
            int i = ib + mf * 16 + g;
            #pragma unroll
            for (int nf = 0; nf < 8; nf++) {
                int j = jb + nf * 8 + 2 * tc;
                float2 e0 = {acc[mf][nf][0], acc[mf][nf][1]};
                float2 e1 = {acc[mf][nf][2], acc[mf][nf][3]};
                *reinterpret_cast<float2*>(&es[i * 132 + j])       = e0;
                *reinterpret_cast<float2*>(&es[(i + 8) * 132 + j]) = e1;
            }
        }
    }
    __syncthreads();

    // softmax (rotation-indexed: conflict-free on stride-132 rows); output tf32-rounded
    if (tid < 128) {
        float* row = es + tid * 132;
        float mx = -1e30f;
        for (int jj = 0; jj < 128; jj++) { int j = (jj + tid) & 127; mx = fmaxf(mx, row[j]); }
        float s = 0.f;
        for (int jj = 0; jj < 128; jj++) { int j = (jj + tid) & 127; float e = __expf(row[j] - mx); row[j] = e; s += e; }
        float inv = 1.f / s;
        for (int jj = 0; jj < 128; jj++) { int j = (jj + tid) & 127; row[j] = f2tff(row[j] * inv); }
    }
    __syncthreads();

    // AV: 4 chunks of 128 channels
    const float* vbase = qbase + (size_t)2 * CQn * NP;
    float* chb = g_ch + (size_t)((b * CC) * HH + h) * WW;
    const unsigned* esu = (const unsigned*)es;
    const unsigned* vbu = (const unsigned*)vb;

    for (int mc = 0; mc < CC; mc += 128) {
        for (int idx = tid; idx < 128 * 128; idx += 256) {
            int ml = idx >> 7, j = idx & 127;
            vb[ml * 132 + j] = f2tff(vbase[(size_t)(mc + ml) * NP + j]);
        }
        __syncthreads();

        float acc[2][8][4];
        #pragma unroll
        for (int mf = 0; mf < 2; mf++)
            #pragma unroll
            for (int nf = 0; nf < 8; nf++)
                #pragma unroll
                for (int r = 0; r < 4; r++) acc[mf][nf][r] = 0.f;

        for (int j0 = 0; j0 < 128; j0 += 8) {
            unsigned af[2][4];
            #pragma unroll
            for (int mf = 0; mf < 2; mf++) {
                int r0 = ib + mf * 16 + g;
                af[mf][0] = esu[(r0    ) * 132 + j0 + tc];
                af[mf][1] = esu[(r0 + 8) * 132 + j0 + tc];
                af[mf][2] = esu[(r0    ) * 132 + j0 + tc + 4];
                af[mf][3] = esu[(r0 + 8) * 132 + j0 + tc + 4];
            }
            unsigned bf[8][2];
            #pragma unroll
            for (int nf = 0; nf < 8; nf++) {
                int m = jb + nf * 8 + g;
                bf[nf][0] = vbu[m * 132 + j0 + tc];
                bf[nf][1] = vbu[m * 132 + j0 + tc + 4];
            }
            #pragma unroll
            for (int mf = 0; mf < 2; mf++)
                #pragma unroll
                for (int nf = 0; nf < 8; nf++)
                    mma_tf32(acc[mf][nf], af[mf], bf[nf]);
        }
        __syncthreads();   // vb consumed; st reuses region

        #pragma unroll
        for (int mf = 0; mf < 2; mf++) {
            int i = ib + mf * 16 + g;
            #pragma unroll
            for (int nf = 0; nf < 8; nf++) {
                int m = jb + nf * 8 + 2 * tc;
                st[m * 132 + i]           = acc[mf][nf][0];
                st[(m + 1) * 132 + i]     = acc[mf][nf][1];
                st[m * 132 + i + 8]       = acc[mf][nf][2];
                st[(m + 1) * 132 + i + 8] = acc[mf][nf][3];
            }
        }
        __syncthreads();
        for (int idx = tid; idx < 128 * 128; idx += 256) {
            int ml = idx >> 7, i = idx & 127;
            chb[(size_t)(mc + ml) * NP + i] = st[ml * 132 + i];
        }
        __syncthreads();
    }
}

// ---------------- kernel 5: vertical attention, tf32 MMA (transposed inputs) ----------------
// energy[i,j] = sum_a q[i>>1][64*(i&1)+a] * k[a][j];  cv[i][128t+p] = sum_j A[i,j] v[4j+t][p]
__global__ __launch_bounds__(256) void v_attn() {
    int bw = blockIdx.x;
    int b = bw >> 7, w = bw & 127;
    extern __shared__ float sm[];
    float* es = sm;                       // [128][132]
    float* r2 = sm + 128 * 132;           // 17536 floats
    float* aq = r2;                       // [128][68]  A: aq[i*68 + a]
    float* kb = r2 + 128 * 68;            // [128][69]  B: kb[j*69 + a]
    float* vb = r2;                       // reuse: [128][133] vb[p*133 + j]
    float* st = r2;                       // reuse: [128][132] st[i*132 + p]

    int tid = threadIdx.x;
    int wid = tid >> 5, lane = tid & 31;
    int wm = wid >> 1, wn = wid & 1;
    int g = lane >> 2, tc = lane & 3;
    int ib = wm * 32, jb = wn * 64;

    const float* qbaseT = g_qkvT + (size_t)b * CO * NP + w * HH;
    const float* kbaseT = qbaseT + (size_t)CQn * NP;

    for (int idx = tid; idx < HH * CQn; idx += 256) {
        int i = idx >> 6, a = idx & 63;
        aq[i * 68 + a] = f2tff(qbaseT[(size_t)(i >> 1) * NP + ((i & 1) << 6) + a]);
    }
    for (int idx = tid; idx < CQn * HH; idx += 256) {
        int a = idx >> 7, j = idx & 127;
        kb[j * 69 + a] = f2tff(kbaseT[(size_t)a * NP + j]);
    }
    __syncthreads();

    {
        const unsigned* aqu = (const unsigned*)aq;
        const unsigned* kbu = (const unsigned*)kb;
        float acc[2][8][4];
        #pragma unroll
        for (int mf = 0; mf < 2; mf++)
            #pragma unroll
            for (int nf = 0; nf < 8; nf++)
                #pragma unroll
                for (int r = 0; r < 4; r++) acc[mf][nf][r] = 0.f;

        for (int a0 = 0; a0 < 64; a0 += 8) {
            unsigned af[2][4];
            #pragma unroll
            for (int mf = 0; mf < 2; mf++) {
                int r0 = ib + mf * 16 + g;
                af[mf][0] = aqu[(r0    ) * 68 + a0 + tc];
                af[mf][1] = aqu[(r0 + 8) * 68 + a0 + tc];
                af[mf][2] = aqu[(r0    ) * 68 + a0 + tc + 4];
                af[mf][3] = aqu[(r0 + 8) * 68 + a0 + tc + 4];
            }
            unsigned bf[8][2];
            #pragma unroll
            for (int nf = 0; nf < 8; nf++) {
                int j = jb + nf * 8 + g;
                bf[nf][0] = kbu[j * 69 + a0 + tc];
                bf[nf][1] = kbu[j * 69 + a0 + tc + 4];
            }
            #pragma unroll
            for (int mf = 0; mf < 2; mf++)
                #pragma unroll
                for (int nf = 0; nf < 8; nf++)
                    mma_tf32(acc[mf][nf], af[mf], bf[nf]);
        }
        #pragma unroll
        for (int mf = 0; mf < 2; mf++) {
            int i = ib + mf * 16 + g;
            #pragma unroll
            for (int nf = 0; nf < 8; nf++) {
                int j = jb + nf * 8 + 2 * tc;
                float2 e0 = {acc[mf][nf][0], acc[mf][nf][1]};
                float2 e1 = {acc[mf][nf][2], acc[mf][nf][3]};
                *reinterpret_cast<float2*>(&es[i * 132 + j])       = e0;
                *reinterpret_cast<float2*>(&es[(i + 8) * 132 + j]) = e1;
            }
        }
    }
    __syncthreads();

    if (tid < 128) {
        float* row = es + tid * 132;
        float mx = -1e30f;
        for (int jj = 0; jj < 128; jj++) { int j = (jj + tid) & 127; mx = fmaxf(mx, row[j]); }
        float s = 0.f;
        for (int jj = 0; jj < 128; jj++) { int j = (jj + tid) & 127; float e = __expf(row[j] - mx); row[j] = e; s += e; }
        float inv = 1.f / s;
        for (int jj = 0; jj < 128; jj++) { int j = (jj + tid) & 127; row[j] = f2tff(row[j] * inv); }
    }
    __syncthreads();

    const float* vbaseT = g_qkvT + (size_t)(b * CO + 2 * CQn) * NP + w * HH;
    float* cvrow = g_cv + (size_t)bw * HH * CC;
    const unsigned* esu = (const unsigned*)es;
    const unsigned* vbu = (const unsigned*)vb;

    for (int t = 0; t < 4; t++) {
        for (int idx = tid; idx < 128 * 128; idx += 256) {
            int j = idx >> 7, p = idx & 127;
            vb[p * 133 + j] = f2tff(vbaseT[(size_t)(4 * j + t) * NP + p]);
        }
        __syncthreads();

        float acc[2][8][4];
        #pragma unroll
        for (int mf = 0; mf < 2; mf++)
            #pragma unroll
            for (int nf = 0; nf < 8; nf++)
                #pragma unroll
                for (int r = 0; r < 4; r++) acc[mf][nf][r] = 0.f;

        for (int j0 = 0; j0 < 128; j0 += 8) {
            unsigned af[2][4];
            #pragma unroll
            for (int mf = 0; mf < 2; mf++) {
                int r0 = ib + mf * 16 + g;
                af[mf][0] = esu[(r0    ) * 132 + j0 + tc];
                af[mf][1] = esu[(r0 + 8) * 132 + j0 + tc];
                af[mf][2] = esu[(r0    ) * 132 + j0 + tc + 4];
                af[mf][3] = esu[(r0 + 8) * 132 + j0 + tc + 4];
            }
            unsigned bf[8][2];
            #pragma unroll
            for (int nf = 0; nf < 8; nf++) {
                int p = jb + nf * 8 + g;
                bf[nf][0] = vbu[p * 133 + j0 + tc];
                bf[nf][1] = vbu[p * 133 + j0 + tc + 4];
            }
            #pragma unroll
            for (int mf = 0; mf < 2; mf++)
                #pragma unroll
                for (int nf = 0; nf < 8; nf++)
                    mma_tf32(acc[mf][nf], af[mf], bf[nf]);
        }
        __syncthreads();   // vb consumed; st reuses region

        #pragma unroll
        for (int mf = 0; mf < 2; mf++) {
            int i = ib + mf * 16 + g;
            #pragma unroll
            for (int nf = 0; nf < 8; nf++) {
                int p = jb + nf * 8 + 2 * tc;
                float2 o0 = {acc[mf][nf][0], acc[mf][nf][1]};
                float2 o1 = {acc[mf][nf][2], acc[mf][nf][3]};
                *reinterpret_cast<float2*>(&st[i * 132 + p])       = o0;
                *reinterpret_cast<float2*>(&st[(i + 8) * 132 + p]) = o1;
            }
        }
        __syncthreads();
        for (int idx = tid; idx < 128 * 128; idx += 256) {
            int i = idx >> 7, p = idx & 127;
            cvrow[(size_t)i * CC + 128 * t + p] = st[i * 132 + p];
        }
        __syncthreads();
    }
}

// ---------------- kernel 6: combine out = gamma*(ch + cv) + x ----------------
__global__ __launch_bounds__(256) void combine_kernel(const float* __restrict__ x,
                                                      const float* __restrict__ gamma,
                                                      float* __restrict__ out) {
    __shared__ float tb[32][33];
    int w0 = blockIdx.x * 32;
    int c0 = blockIdx.y * 32;
    int bh = blockIdx.z;
    int b = bh >> 7, h = bh & 127;
    int tx = threadIdx.x, ty = threadIdx.y;

    for (int r = ty; r < 32; r += 8) {
        int w = w0 + r;
        tb[r][tx] = g_cv[(size_t)((b * WW + w) * HH + h) * CC + c0 + tx];
    }
    __syncthreads();
    float gv = gamma[0];
    for (int r = ty; r < 32; r += 8) {
        int c = c0 + r;
        int w = w0 + tx;
        size_t o = (size_t)((b * CC + c) * HH + h) * WW + w;
        out[o] = gv * (g_ch[o] + tb[tx][r]) + x[o];
    }
}

// ---------------- launch ----------------
extern "C" void kernel_launch(void* const* d_in, const int* in_sizes, int n_in,
                              void* d_out, int out_size) {
    const float* x     = (const float*)d_in[0];
    const float* Wq    = (const float*)d_in[1];
    const float* bq    = (const float*)d_in[2];
    const float* Wk    = (const float*)d_in[3];
    const float* bk    = (const float*)d_in[4];
    const float* Wv    = (const float*)d_in[5];
    const float* bv    = (const float*)d_in[6];
    const float* gamma = (const float*)d_in[7];
    float* out = (float*)d_out;

    const int HSMEM = (128 * 132 + 17408) * 4;   // 137216 B
    const int VSMEM = (128 * 132 + 17536) * 4;   // 137728 B
    cudaFuncSetAttribute(h_attn, cudaFuncAttributeMaxDynamicSharedMemorySize, HSMEM);
    cudaFuncSetAttribute(v_attn, cudaFuncAttributeMaxDynamicSharedMemorySize, VSMEM);

    pack_kernel<<<(CO * CC + 255) / 256, 256>>>(Wq, bq, Wk, bk, Wv, bv);
    qkv_gemm<<<dim3(5, 128, 4), 256>>>(x);
    transpose_hw<<<dim3(4, 4, BB * CO), dim3(32, 8, 1)>>>();
    h_attn<<<BB * HH, 256, HSMEM>>>();
    v_attn<<<BB * WW, 256, VSMEM>>>();
    combine_kernel<<<dim3(WW / 32, CC / 32, BB * HH), dim3(32, 8, 1)>>>(x, gamma, out);
}

// round 3
// speedup vs baseline: 2.9913x; 1.4513x over previous
#include <cuda_runtime.h>

#define CC 512
#define CQn 64
#define HH 128
#define WW 128
#define BB 4
#define CO 640
#define NP (HH*WW)

// ---------------- scratch ----------------
__device__ float g_qkv [(size_t)BB*CO*NP];     // (b, o, h, w)
__device__ float g_qkvT[(size_t)BB*CO*NP];     // (b, o, w, h)
__device__ float g_ch  [(size_t)BB*HH*WW*CC];  // [bh][w][c]
__device__ float g_cv  [(size_t)BB*WW*HH*CC];  // [(b*W+w)][h][c]
__device__ float g_Wall[CO*CC];
__device__ float g_ball[CO];

// ---------------- helpers ----------------
__device__ __forceinline__ float f2tff(float f) {
    unsigned u; asm("cvt.rna.tf32.f32 %0, %1;" : "=r"(u) : "f"(f)); return __uint_as_float(u);
}
__device__ __forceinline__ unsigned bf2pack(float lo, float hi) {
    unsigned r; asm("cvt.rn.bf16x2.f32 %0, %1, %2;" : "=r"(r) : "f"(hi), "f"(lo)); return r;
}
__device__ __forceinline__ void mma_tf32(float c[4], const unsigned a[4], const unsigned b[2]) {
    asm volatile("mma.sync.aligned.m16n8k8.row.col.f32.tf32.tf32.f32 "
        "{%0,%1,%2,%3}, {%4,%5,%6,%7}, {%8,%9}, {%0,%1,%2,%3};"
        : "+f"(c[0]), "+f"(c[1]), "+f"(c[2]), "+f"(c[3])
        : "r"(a[0]), "r"(a[1]), "r"(a[2]), "r"(a[3]), "r"(b[0]), "r"(b[1]));
}
__device__ __forceinline__ void mma_bf16(float c[4], const unsigned a[4], const unsigned b[2]) {
    asm volatile("mma.sync.aligned.m16n8k16.row.col.f32.bf16.bf16.f32 "
        "{%0,%1,%2,%3}, {%4,%5,%6,%7}, {%8,%9}, {%0,%1,%2,%3};"
        : "+f"(c[0]), "+f"(c[1]), "+f"(c[2]), "+f"(c[3])
        : "r"(a[0]), "r"(a[1]), "r"(a[2]), "r"(a[3]), "r"(b[0]), "r"(b[1]));
}
__device__ __forceinline__ void cpa16(void* dst, const void* src) {
    unsigned d = (unsigned)__cvta_generic_to_shared(dst);
    asm volatile("cp.async.ca.shared.global [%0], [%1], 16;" :: "r"(d), "l"(src));
}

// ---------------- kernel 1: pack weights ----------------
__global__ void pack_kernel(const float* __restrict__ Wq, const float* __restrict__ bq,
                            const float* __restrict__ Wk, const float* __restrict__ bk,
                            const float* __restrict__ Wv, const float* __restrict__ bv) {
    int idx = blockIdx.x * blockDim.x + threadIdx.x;
    if (idx < CO * CC) {
        int o = idx / CC, c = idx % CC;
        float v;
        if (o < CQn)            v = Wq[o * CC + c];
        else if (o < 2 * CQn)   v = Wk[(o - CQn) * CC + c];
        else                    v = Wv[(o - 2 * CQn) * CC + c];
        g_Wall[idx] = f2tff(v);
    }
    if (idx < CO)
        g_ball[idx] = (idx < CQn) ? bq[idx] : (idx < 2 * CQn) ? bk[idx - CQn] : bv[idx - 2 * CQn];
}

// ---------------- kernel 2: QKV GEMM (tf32, cp.async double-buffered) ----------------
__global__ __launch_bounds__(256) void qkv_gemm(const float* __restrict__ x) {
    __shared__ float As[2][128 * 20];
    __shared__ float Bs[2][16 * 136];

    int m0 = blockIdx.x * 128;
    int n0 = blockIdx.y * 128;
    int b  = blockIdx.z;

    const float* A = g_Wall;
    const float* B = x + (size_t)b * CC * NP;
    float*       Cp = g_qkv + (size_t)b * CO * NP;

    int tid = threadIdx.x;
    int wid = tid >> 5, lane = tid & 31;
    int wm = wid >> 1, wn = wid & 1;
    int g = lane >> 2, tc = lane & 3;

    int arow = tid >> 2, acol = (tid & 3) * 4;
    int brow = tid >> 5, bcol = lane * 4;

    float acc[2][8][4];
    #pragma unroll
    for (int mf = 0; mf < 2; mf++)
        #pragma unroll
        for (int nf = 0; nf < 8; nf++)
            #pragma unroll
            for (int r = 0; r < 4; r++) acc[mf][nf][r] = 0.f;

    // prologue: stage k0=0 into buf 0
    #pragma unroll
    for (int h = 0; h < 2; h++) {
        cpa16(&As[0][(arow + h * 64) * 20 + acol], &A[(size_t)(m0 + arow + h * 64) * CC + acol]);
        cpa16(&Bs[0][(brow + h * 8) * 136 + bcol], &B[(size_t)(brow + h * 8) * NP + n0 + bcol]);
    }
    asm volatile("cp.async.commit_group;");
    asm volatile("cp.async.wait_group 0;");
    __syncthreads();

    for (int k0 = 0; k0 < CC; k0 += 16) {
        int buf = (k0 >> 4) & 1;
        if (k0 + 16 < CC) {
            #pragma unroll
            for (int h = 0; h < 2; h++) {
                cpa16(&As[buf ^ 1][(arow + h * 64) * 20 + acol],
                      &A[(size_t)(m0 + arow + h * 64) * CC + k0 + 16 + acol]);
                cpa16(&Bs[buf ^ 1][(brow + h * 8) * 136 + bcol],
                      &B[(size_t)(k0 + 16 + brow + h * 8) * NP + n0 + bcol]);
            }
            asm volatile("cp.async.commit_group;");
        }
        const unsigned* Asu = (const unsigned*)As[buf];
        const unsigned* Bsu = (const unsigned*)Bs[buf];
        #pragma unroll
        for (int ks = 0; ks < 16; ks += 8) {
            unsigned af[2][4];
            #pragma unroll
            for (int mf = 0; mf < 2; mf++) {
                int r0 = wm * 32 + mf * 16 + g;
                af[mf][0] = Asu[(r0    ) * 20 + ks + tc];
                af[mf][1] = Asu[(r0 + 8) * 20 + ks + tc];
                af[mf][2] = Asu[(r0    ) * 20 + ks + tc + 4];
                af[mf][3] = Asu[(r0 + 8) * 20 + ks + tc + 4];
            }
            unsigned bf[8][2];
            #pragma unroll
            for (int nf = 0; nf < 8; nf++) {
                int nn = wn * 64 + nf * 8 + g;
                bf[nf][0] = Bsu[(ks + tc    ) * 136 + nn];
                bf[nf][1] = Bsu[(ks + tc + 4) * 136 + nn];
            }
            #pragma unroll
            for (int mf = 0; mf < 2; mf++)
                #pragma unroll
                for (int nf = 0; nf < 8; nf++)
                    mma_tf32(acc[mf][nf], af[mf], bf[nf]);
        }
        if (k0 + 16 < CC) asm volatile("cp.async.wait_group 0;");
        __syncthreads();
    }

    #pragma unroll
    for (int mf = 0; mf < 2; mf++) {
        int i0 = m0 + wm * 32 + mf * 16 + g;
        float bv0 = g_ball[i0], bv1 = g_ball[i0 + 8];
        #pragma unroll
        for (int nf = 0; nf < 8; nf++) {
            int j = n0 + wn * 64 + nf * 8 + 2 * tc;
            float2 o0, o1;
            o0.x = acc[mf][nf][0] + bv0; o0.y = acc[mf][nf][1] + bv0;
            o1.x = acc[mf][nf][2] + bv1; o1.y = acc[mf][nf][3] + bv1;
            *reinterpret_cast<float2*>(&Cp[(size_t)i0 * NP + j])       = o0;
            *reinterpret_cast<float2*>(&Cp[(size_t)(i0 + 8) * NP + j]) = o1;
        }
    }
}

// ---------------- kernel 3: per-plane (H,W) transpose ----------------
__global__ __launch_bounds__(256) void transpose_hw() {
    __shared__ float t[32][33];
    int plane = blockIdx.z;
    const float* src = g_qkv + (size_t)plane * NP;
    float*       dst = g_qkvT + (size_t)plane * NP;
    int w0 = blockIdx.x * 32, h0 = blockIdx.y * 32;
    int tx = threadIdx.x, ty = threadIdx.y;
    #pragma unroll
    for (int r = 0; r < 32; r += 8)
        t[ty + r][tx] = src[(size_t)(h0 + ty + r) * WW + w0 + tx];
    __syncthreads();
    #pragma unroll
    for (int r = 0; r < 32; r += 8)
        dst[(size_t)(w0 + ty + r) * HH + h0 + tx] = t[tx][ty + r];
}

// =============== shared attention machinery (512 threads, 16 warps) ===============
// smem: es[128*132] f32 | ebu[128*68] u32 (bf16x2 probs) | region[17408] f32
//   region phase1: qs/aq [64*136 or 128*68] + kb [128*68]
//   region phase2: vbu [256*68] u32 (bf16x2 V chunk)

__device__ __forceinline__ void warp_softmax_bf16(float* es, unsigned* ebu, int wid, int lane) {
    #pragma unroll
    for (int r = 0; r < 8; r++) {
        int row = wid * 8 + r;
        float4 v4 = *reinterpret_cast<const float4*>(&es[row * 132 + 4 * lane]);
        float mx = fmaxf(fmaxf(v4.x, v4.y), fmaxf(v4.z, v4.w));
        #pragma unroll
        for (int o = 16; o; o >>= 1) mx = fmaxf(mx, __shfl_xor_sync(0xffffffffu, mx, o));
        float e0 = __expf(v4.x - mx), e1 = __expf(v4.y - mx);
        float e2 = __expf(v4.z - mx), e3 = __expf(v4.w - mx);
        float s = e0 + e1 + e2 + e3;
        #pragma unroll
        for (int o = 16; o; o >>= 1) s += __shfl_xor_sync(0xffffffffu, s, o);
        float inv = 1.f / s;
        uint2 w2;
        w2.x = bf2pack(e0 * inv, e1 * inv);
        w2.y = bf2pack(e2 * inv, e3 * inv);
        *reinterpret_cast<uint2*>(&ebu[row * 68 + 2 * lane]) = w2;
    }
}

// energy MMA (tf32): A from aA (layout flag), B from kb[j*68+a], out -> es
// aKmajor=1: A stored [a][i] stride 136 ; aKmajor=0: A stored [i][a] stride 68
template<int AKMAJOR>
__device__ __forceinline__ void energy_mma(const unsigned* aA, const unsigned* kbu, float* es,
                                           int ib, int jb, int g, int tc) {
    float acc[2][4][4];
    #pragma unroll
    for (int mf = 0; mf < 2; mf++)
        #pragma unroll
        for (int nf = 0; nf < 4; nf++)
            #pragma unroll
            for (int r = 0; r < 4; r++) acc[mf][nf][r] = 0.f;

    for (int a0 = 0; a0 < 64; a0 += 8) {
        unsigned af[2][4];
        #pragma unroll
        for (int mf = 0; mf < 2; mf++) {
            int r0 = ib + mf * 16 + g;
            if (AKMAJOR) {
                af[mf][0] = aA[(a0 + tc    ) * 136 + r0];
                af[mf][1] = aA[(a0 + tc    ) * 136 + r0 + 8];
                af[mf][2] = aA[(a0 + tc + 4) * 136 + r0];
                af[mf][3] = aA[(a0 + tc + 4) * 136 + r0 + 8];
            } else {
                af[mf][0] = aA[(r0    ) * 68 + a0 + tc];
                af[mf][1] = aA[(r0 + 8) * 68 + a0 + tc];
                af[mf][2] = aA[(r0    ) * 68 + a0 + tc + 4];
                af[mf][3] = aA[(r0 + 8) * 68 + a0 + tc + 4];
            }
        }
        unsigned bf[4][2];
        #pragma unroll
        for (int nf = 0; nf < 4; nf++) {
            int j = jb + nf * 8 + g;
            bf[nf][0] = kbu[j * 68 + a0 + tc];
            bf[nf][1] = kbu[j * 68 + a0 + tc + 4];
        }
        #pragma unroll
        for (int mf = 0; mf < 2; mf++)
            #pragma unroll
            for (int nf = 0; nf < 4; nf++)
                mma_tf32(acc[mf][nf], af[mf], bf[nf]);
    }
    #pragma unroll
    for (int mf = 0; mf < 2; mf++) {
        int i = ib + mf * 16 + g;
        #pragma unroll
        for (int nf = 0; nf < 4; nf++) {
            int j = jb + nf * 8 + 2 * tc;
            float2 e0 = {acc[mf][nf][0], acc[mf][nf][1]};
            float2 e1 = {acc[mf][nf][2], acc[mf][nf][3]};
            *reinterpret_cast<float2*>(&es[i * 132 + j])       = e0;
            *reinterpret_cast<float2*>(&es[(i + 8) * 132 + j]) = e1;
        }
    }
}

// AV MMA (bf16): probs ebu[128*68], V chunk vbu[256 rows * 68], direct global writes
__device__ __forceinline__ void av_mma_chunk(const unsigned* ebu, const unsigned* vbu,
                                             float* outb, int mglob0,
                                             int ib, int mb, int g, int tc) {
    float acc[2][8][4];
    #pragma unroll
    for (int mf = 0; mf < 2; mf++)
        #pragma unroll
        for (int nf = 0; nf < 8; nf++)
            #pragma unroll
            for (int r = 0; r < 4; r++) acc[mf][nf][r] = 0.f;

    for (int j0 = 0; j0 < 128; j0 += 16) {
        int u0 = j0 >> 1;
        unsigned af[2][4];
        #pragma unroll
        for (int mf = 0; mf < 2; mf++) {
            int r0 = ib + mf * 16 + g;
            af[mf][0] = ebu[(r0    ) * 68 + u0 + tc];
            af[mf][1] = ebu[(r0 + 8) * 68 + u0 + tc];
            af[mf][2] = ebu[(r0    ) * 68 + u0 + tc + 4];
            af[mf][3] = ebu[(r0 + 8) * 68 + u0 + tc + 4];
        }
        unsigned bf[8][2];
        #pragma unroll
        for (int nf = 0; nf < 8; nf++) {
            int m = mb + nf * 8 + g;
            bf[nf][0] = vbu[m * 68 + u0 + tc];
            bf[nf][1] = vbu[m * 68 + u0 + tc + 4];
        }
        #pragma unroll
        for (int mf = 0; mf < 2; mf++)
            #pragma unroll
            for (int nf = 0; nf < 8; nf++)
                mma_bf16(acc[mf][nf], af[mf], bf[nf]);
    }
    #pragma unroll
    for (int mf = 0; mf < 2; mf++) {
        int i = ib + mf * 16 + g;
        #pragma unroll
        for (int nf = 0; nf < 8; nf++) {
            int m = mglob0 + mb + nf * 8 + 2 * tc;
            float2 o0 = {acc[mf][nf][0], acc[mf][nf][1]};
            float2 o1 = {acc[mf][nf][2], acc[mf][nf][3]};
            *reinterpret_cast<float2*>(&outb[(size_t)i * CC + m])       = o0;
            *reinterpret_cast<float2*>(&outb[(size_t)(i + 8) * CC + m]) = o1;
        }
    }
}

// ---------------- kernel 4: horizontal attention ----------------
__global__ __launch_bounds__(512) void h_attn() {
    int bh = blockIdx.x;
    int b = bh >> 7, h = bh & 127;
    extern __shared__ float sm[];
    float*    es  = sm;                                // 16896 f
    unsigned* ebu = (unsigned*)(sm + 16896);           // 8704 w
    float*    r2  = sm + 16896 + 8704;                 // 17408 f
    float*    qs  = r2;                                // [a][i] stride 136
    float*    kb  = r2 + 8704;                         // [j][a] stride 68
    unsigned* vbu = (unsigned*)r2;                     // [256][68] bf16x2

    int tid = threadIdx.x;
    int wid = tid >> 5, lane = tid & 31;
    int wr = wid >> 2, wc = wid & 3;
    int g = lane >> 2, tc = lane & 3;
    int ib = wr * 32;

    const float* qbase = g_qkv + (size_t)b * CO * NP + h * WW;
    const float* kbase = qbase + (size_t)CQn * NP;

    for (int idx = tid; idx < CQn * WW; idx += 512) {
        int a = idx >> 7, i = idx & 127;
        qs[a * 136 + i] = f2tff(qbase[(size_t)a * NP + i]);
    }
    for (int idx = tid; idx < CQn * WW; idx += 512) {
        int c = idx >> 7, w = idx & 127;
        kb[(((w & 1) << 6) + c) * 68 + (w >> 1)] = f2tff(kbase[(size_t)c * NP + w]);
    }
    __syncthreads();

    energy_mma<1>((const unsigned*)qs, (const unsigned*)kb, es, ib, wc * 32, g, tc);
    __syncthreads();

    warp_softmax_bf16(es, ebu, wid, lane);
    __syncthreads();

    const float* vbase = qbase + (size_t)2 * CQn * NP;
    float* chb = g_ch + (size_t)bh * WW * CC;          // [i(w)][c]
    for (int mc = 0; mc < CC; mc += 256) {
        for (int idx = tid; idx < 256 * 64; idx += 512) {
            int ml = idx >> 6, u = idx & 63;
            float2 vv = *reinterpret_cast<const float2*>(&vbase[(size_t)(mc + ml) * NP + 2 * u]);
            vbu[ml * 68 + u] = bf2pack(vv.x, vv.y);
        }
        __syncthreads();
        av_mma_chunk(ebu, vbu, chb, mc, ib, wc * 64, g, tc);
        __syncthreads();
    }
}

// ---------------- kernel 5: vertical attention ----------------
__global__ __launch_bounds__(512) void v_attn() {
    int bw = blockIdx.x;
    int b = bw >> 7, w = bw & 127;
    extern __shared__ float sm[];
    float*    es  = sm;
    unsigned* ebu = (unsigned*)(sm + 16896);
    float*    r2  = sm + 16896 + 8704;
    float*    aq  = r2;                                // [i][a] stride 68
    float*    kb  = r2 + 8704;                         // [j][a] stride 68
    unsigned* vbu = (unsigned*)r2;                     // [256][68]

    int tid = threadIdx.x;
    int wid = tid >> 5, lane = tid & 31;
    int wr = wid >> 2, wc = wid & 3;
    int g = lane >> 2, tc = lane & 3;
    int ib = wr * 32;

    const float* qbaseT = g_qkvT + (size_t)b * CO * NP + w * HH;
    const float* kbaseT = qbaseT + (size_t)CQn * NP;

    for (int idx = tid; idx < HH * CQn; idx += 512) {
        int i = idx >> 6, a = idx & 63;
        aq[i * 68 + a] = f2tff(qbaseT[(size_t)(i >> 1) * NP + ((i & 1) << 6) + a]);
    }
    for (int idx = tid; idx < CQn * HH; idx += 512) {
        int a = idx >> 7, j = idx & 127;
        kb[j * 68 + a] = f2tff(kbaseT[(size_t)a * NP + j]);
    }
    __syncthreads();

    energy_mma<0>((const unsigned*)aq, (const unsigned*)kb, es, ib, wc * 32, g, tc);
    __syncthreads();

    warp_softmax_bf16(es, ebu, wid, lane);
    __syncthreads();

    const float* vbaseT = g_qkvT + (size_t)(b * CO + 2 * CQn) * NP + w * HH;
    float* cvb = g_cv + (size_t)bw * HH * CC;          // [i(h)][c]
    for (int cp = 0; cp < 2; cp++) {
        // vbu[(tl*128+p)][u] = bf16x2( v[8u+t][p], v[8u+4+t][p] ), t = 2cp+tl
        for (int idx = tid; idx < 256 * 64; idx += 512) {
            int p = idx & 127, tl = (idx >> 7) & 1, u = idx >> 8;
            int t = cp * 2 + tl;
            float f0 = vbaseT[(size_t)(8 * u + t) * NP + p];
            float f1 = vbaseT[(size_t)(8 * u + 4 + t) * NP + p];
            vbu[(tl * 128 + p) * 68 + u] = bf2pack(f0, f1);
        }
        __syncthreads();
        av_mma_chunk(ebu, vbu, cvb, cp * 256, ib, wc * 64, g, tc);
        __syncthreads();
    }
}

// ---------------- kernel 6: combine ----------------
// out[b][c][h][w] = gamma*(ch[bh][w][c] + cv[bw][h][c]) + x[b][c][h][w]
__global__ __launch_bounds__(256) void combine_kernel(const float* __restrict__ x,
                                                      const float* __restrict__ gamma,
                                                      float* __restrict__ out) {
    __shared__ float tb[32][33];
    int w0 = blockIdx.x * 32;
    int c0 = blockIdx.y * 32;
    int bh = blockIdx.z;
    int b = bh >> 7, h = bh & 127;
    int tx = threadIdx.x, ty = threadIdx.y;

    for (int r = ty; r < 32; r += 8) {
        int w = w0 + r;
        float chv = g_ch[((size_t)bh * WW + w) * CC + c0 + tx];
        float cvv = g_cv[(((size_t)(b * WW + w)) * HH + h) * CC + c0 + tx];
        tb[r][tx] = chv + cvv;
    }
    __syncthreads();
    float gv = gamma[0];
    for (int r = ty; r < 32; r += 8) {
        int c = c0 + r;
        int w = w0 + tx;
        size_t o = (size_t)((b * CC + c) * HH + h) * WW + w;
        out[o] = gv * tb[tx][r] + x[o];
    }
}

// ---------------- launch ----------------
extern "C" void kernel_launch(void* const* d_in, const int* in_sizes, int n_in,
                              void* d_out, int out_size) {
    const float* x     = (const float*)d_in[0];
    const float* Wq    = (const float*)d_in[1];
    const float* bq    = (const float*)d_in[2];
    const float* Wk    = (const float*)d_in[3];
    const float* bk    = (const float*)d_in[4];
    const float* Wv    = (const float*)d_in[5];
    const float* bv    = (const float*)d_in[6];
    const float* gamma = (const float*)d_in[7];
    float* out = (float*)d_out;

    const int ASMEM = (16896 + 8704 + 17408) * 4;   // 172032 B
    cudaFuncSetAttribute(h_attn, cudaFuncAttributeMaxDynamicSharedMemorySize, ASMEM);
    cudaFuncSetAttribute(v_attn, cudaFuncAttributeMaxDynamicSharedMemorySize, ASMEM);

    pack_kernel<<<(CO * CC + 255) / 256, 256>>>(Wq, bq, Wk, bk, Wv, bv);
    qkv_gemm<<<dim3(5, 128, 4), 256>>>(x);
    transpose_hw<<<dim3(4, 4, BB * CO), dim3(32, 8, 1)>>>();
    h_attn<<<BB * HH, 512, ASMEM>>>();
    v_attn<<<BB * WW, 512, ASMEM>>>();
    combine_kernel<<<dim3(WW / 32, CC / 32, BB * HH), dim3(32, 8, 1)>>>(x, gamma, out);
}

// round 4
// speedup vs baseline: 3.5340x; 1.1814x over previous
#include <cuda_runtime.h>

#define CC 512
#define CQn 64
#define HH 128
#define WW 128
#define BB 4
#define CO 640
#define NP (HH*WW)

// ---------------- scratch ----------------
__device__ __align__(256) float    g_qkv [(size_t)BB*128*NP];      // (b, o<128, h, w) f32: q 0..63, k 64..127
__device__ __align__(256) float    g_qkvT[(size_t)BB*128*NP];      // (b, o<128, w, h)
__device__ __align__(256) unsigned g_v   [(size_t)BB*CC*NP/2];     // (b, o, h, w) bf16 pairs along w
__device__ __align__(256) unsigned g_vT  [(size_t)BB*CC*NP/2];     // (b, o, w, h) bf16 pairs along h
__device__ __align__(256) unsigned g_ch  [(size_t)BB*HH*WW*CC/2];  // [bh][w][c] bf16
__device__ __align__(256) unsigned g_cv  [(size_t)BB*WW*HH*CC/2];  // [bw][h][c] bf16
__device__ float g_Wall[CO*CC];
__device__ float g_ball[CO];

// ---------------- helpers ----------------
__device__ __forceinline__ float f2tff(float f) {
    unsigned u; asm("cvt.rna.tf32.f32 %0, %1;" : "=r"(u) : "f"(f)); return __uint_as_float(u);
}
__device__ __forceinline__ unsigned bf2pack(float lo, float hi) {
    unsigned r; asm("cvt.rn.bf16x2.f32 %0, %1, %2;" : "=r"(r) : "f"(hi), "f"(lo)); return r;
}
__device__ __forceinline__ void mma_tf32(float c[4], const unsigned a[4], const unsigned b[2]) {
    asm volatile("mma.sync.aligned.m16n8k8.row.col.f32.tf32.tf32.f32 "
        "{%0,%1,%2,%3}, {%4,%5,%6,%7}, {%8,%9}, {%0,%1,%2,%3};"
        : "+f"(c[0]), "+f"(c[1]), "+f"(c[2]), "+f"(c[3])
        : "r"(a[0]), "r"(a[1]), "r"(a[2]), "r"(a[3]), "r"(b[0]), "r"(b[1]));
}
__device__ __forceinline__ void mma_bf16(float c[4], const unsigned a[4], const unsigned b[2]) {
    asm volatile("mma.sync.aligned.m16n8k16.row.col.f32.bf16.bf16.f32 "
        "{%0,%1,%2,%3}, {%4,%5,%6,%7}, {%8,%9}, {%0,%1,%2,%3};"
        : "+f"(c[0]), "+f"(c[1]), "+f"(c[2]), "+f"(c[3])
        : "r"(a[0]), "r"(a[1]), "r"(a[2]), "r"(a[3]), "r"(b[0]), "r"(b[1]));
}
__device__ __forceinline__ void cpa16(void* dst, const void* src) {
    unsigned d = (unsigned)__cvta_generic_to_shared(dst);
    asm volatile("cp.async.ca.shared.global [%0], [%1], 16;" :: "r"(d), "l"(src));
}

// ---------------- kernel 1: pack weights ----------------
__global__ void pack_kernel(const float* __restrict__ Wq, const float* __restrict__ bq,
                            const float* __restrict__ Wk, const float* __restrict__ bk,
                            const float* __restrict__ Wv, const float* __restrict__ bv) {
    int idx = blockIdx.x * blockDim.x + threadIdx.x;
    if (idx < CO * CC) {
        int o = idx / CC, c = idx % CC;
        float v;
        if (o < CQn)            v = Wq[o * CC + c];
        else if (o < 2 * CQn)   v = Wk[(o - CQn) * CC + c];
        else                    v = Wv[(o - 2 * CQn) * CC + c];
        g_Wall[idx] = f2tff(v);
    }
    if (idx < CO)
        g_ball[idx] = (idx < CQn) ? bq[idx] : (idx < 2 * CQn) ? bk[idx - CQn] : bv[idx - 2 * CQn];
}

// ---------------- kernel 2: QKV GEMM (tf32, cp.async double-buffered) ----------------
// tile m0=0: q,k -> g_qkv f32. tiles m0>=128: V -> g_v bf16.
__global__ __launch_bounds__(256) void qkv_gemm(const float* __restrict__ x) {
    __shared__ float As[2][128 * 20];
    __shared__ float Bs[2][16 * 136];

    int m0 = blockIdx.x * 128;
    int n0 = blockIdx.y * 128;
    int b  = blockIdx.z;

    const float* A = g_Wall;
    const float* B = x + (size_t)b * CC * NP;

    int tid = threadIdx.x;
    int wid = tid >> 5, lane = tid & 31;
    int wm = wid >> 1, wn = wid & 1;
    int g = lane >> 2, tc = lane & 3;

    int arow = tid >> 2, acol = (tid & 3) * 4;
    int brow = tid >> 5, bcol = lane * 4;

    float acc[2][8][4];
    #pragma unroll
    for (int mf = 0; mf < 2; mf++)
        #pragma unroll
        for (int nf = 0; nf < 8; nf++)
            #pragma unroll
            for (int r = 0; r < 4; r++) acc[mf][nf][r] = 0.f;

    #pragma unroll
    for (int h = 0; h < 2; h++) {
        cpa16(&As[0][(arow + h * 64) * 20 + acol], &A[(size_t)(m0 + arow + h * 64) * CC + acol]);
        cpa16(&Bs[0][(brow + h * 8) * 136 + bcol], &B[(size_t)(brow + h * 8) * NP + n0 + bcol]);
    }
    asm volatile("cp.async.commit_group;");
    asm volatile("cp.async.wait_group 0;");
    __syncthreads();

    for (int k0 = 0; k0 < CC; k0 += 16) {
        int buf = (k0 >> 4) & 1;
        if (k0 + 16 < CC) {
            #pragma unroll
            for (int h = 0; h < 2; h++) {
                cpa16(&As[buf ^ 1][(arow + h * 64) * 20 + acol],
                      &A[(size_t)(m0 + arow + h * 64) * CC + k0 + 16 + acol]);
                cpa16(&Bs[buf ^ 1][(brow + h * 8) * 136 + bcol],
                      &B[(size_t)(k0 + 16 + brow + h * 8) * NP + n0 + bcol]);
            }
            asm volatile("cp.async.commit_group;");
        }
        const unsigned* Asu = (const unsigned*)As[buf];
        const unsigned* Bsu = (const unsigned*)Bs[buf];
        #pragma unroll
        for (int ks = 0; ks < 16; ks += 8) {
            unsigned af[2][4];
            #pragma unroll
            for (int mf = 0; mf < 2; mf++) {
                int r0 = wm * 32 + mf * 16 + g;
                af[mf][0] = Asu[(r0    ) * 20 + ks + tc];
                af[mf][1] = Asu[(r0 + 8) * 20 + ks + tc];
                af[mf][2] = Asu[(r0    ) * 20 + ks + tc + 4];
                af[mf][3] = Asu[(r0 + 8) * 20 + ks + tc + 4];
            }
            unsigned bf[8][2];
            #pragma unroll
            for (int nf = 0; nf < 8; nf++) {
                int nn = wn * 64 + nf * 8 + g;
                bf[nf][0] = Bsu[(ks + tc    ) * 136 + nn];
                bf[nf][1] = Bsu[(ks + tc + 4) * 136 + nn];
            }
            #pragma unroll
            for (int mf = 0; mf < 2; mf++)
                #pragma unroll
                for (int nf = 0; nf < 8; nf++)
                    mma_tf32(acc[mf][nf], af[mf], bf[nf]);
        }
        if (k0 + 16 < CC) asm volatile("cp.async.wait_group 0;");
        __syncthreads();
    }

    #pragma unroll
    for (int mf = 0; mf < 2; mf++) {
        int i0 = m0 + wm * 32 + mf * 16 + g;
        float bv0 = g_ball[i0], bv1 = g_ball[i0 + 8];
        #pragma unroll
        for (int nf = 0; nf < 8; nf++) {
            int j = n0 + wn * 64 + nf * 8 + 2 * tc;
            float o00 = acc[mf][nf][0] + bv0, o01 = acc[mf][nf][1] + bv0;
            float o10 = acc[mf][nf][2] + bv1, o11 = acc[mf][nf][3] + bv1;
            if (m0 == 0) {
                float* Cp = g_qkv + (size_t)b * 128 * NP;
                float2 w0 = {o00, o01}, w1 = {o10, o11};
                *reinterpret_cast<float2*>(&Cp[(size_t)i0 * NP + j])       = w0;
                *reinterpret_cast<float2*>(&Cp[(size_t)(i0 + 8) * NP + j]) = w1;
            } else {
                unsigned* vp = g_v + (size_t)b * CC * (NP / 2);
                vp[(size_t)(i0 - 128) * (NP / 2) + (j >> 1)] = bf2pack(o00, o01);
                vp[(size_t)(i0 - 120) * (NP / 2) + (j >> 1)] = bf2pack(o10, o11);
            }
        }
    }
}

// ---------------- kernel 3a: f32 (H,W) transpose for q,k planes ----------------
__global__ __launch_bounds__(256) void transpose_qk() {
    __shared__ float t[32][33];
    int plane = blockIdx.z;
    const float* src = g_qkv + (size_t)plane * NP;
    float*       dst = g_qkvT + (size_t)plane * NP;
    int w0 = blockIdx.x * 32, h0 = blockIdx.y * 32;
    int tx = threadIdx.x, ty = threadIdx.y;
    #pragma unroll
    for (int r = 0; r < 32; r += 8)
        t[ty + r][tx] = src[(size_t)(h0 + ty + r) * WW + w0 + tx];
    __syncthreads();
    #pragma unroll
    for (int r = 0; r < 32; r += 8)
        dst[(size_t)(w0 + ty + r) * HH + h0 + tx] = t[tx][ty + r];
}

// ---------------- kernel 3b: bf16 (H,W) transpose for V planes (64x64 u32 tiles) ----------------
__global__ __launch_bounds__(256) void transpose_v() {
    __shared__ unsigned t[64][33];
    int plane = blockIdx.z;
    const unsigned* src = g_v + (size_t)plane * (NP / 2);
    unsigned*       dst = g_vT + (size_t)plane * (NP / 2);
    int h0 = blockIdx.y * 64, w0 = blockIdx.x * 64;
    int tx = threadIdx.x & 31, ty = threadIdx.x >> 5;
    #pragma unroll
    for (int h = ty; h < 64; h += 8)
        t[h][tx] = src[(size_t)(h0 + h) * 64 + (w0 >> 1) + tx];
    __syncthreads();
    #pragma unroll
    for (int w = ty; w < 64; w += 8) {
        unsigned a = t[2 * tx][w >> 1], b = t[2 * tx + 1][w >> 1];
        unsigned r = (w & 1) ? __byte_perm(a, b, 0x7632) : __byte_perm(a, b, 0x5410);
        dst[(size_t)(w0 + w) * 64 + (h0 >> 1) + tx] = r;
    }
}

// =============== attention machinery (512 threads, 16 warps) ===============

// energy (tf32) fully in registers + softmax; bf16 probs -> ebu[128][68]
// AKMAJOR=1: A stored [a][i] stride 136 (h). AKMAJOR=0: A stored [i][a] stride 68 (v).
template<int AKMAJOR>
__device__ __forceinline__ void energy_softmax(const unsigned* aA, const unsigned* kbu,
                                               unsigned* ebu, float2* pm, int wid, int lane) {
    int wr8 = wid >> 1, wc2 = wid & 1;
    int ib = wr8 * 16, jb = wc2 * 64, jb2 = wc2 * 32;
    int g = lane >> 2, tc = lane & 3;

    float acc[8][4];
    #pragma unroll
    for (int nf = 0; nf < 8; nf++)
        #pragma unroll
        for (int r = 0; r < 4; r++) acc[nf][r] = 0.f;

    for (int a0 = 0; a0 < 64; a0 += 8) {
        unsigned af[4];
        if (AKMAJOR) {
            af[0] = aA[(a0 + tc    ) * 136 + ib + g];
            af[1] = aA[(a0 + tc    ) * 136 + ib + g + 8];
            af[2] = aA[(a0 + tc + 4) * 136 + ib + g];
            af[3] = aA[(a0 + tc + 4) * 136 + ib + g + 8];
        } else {
            af[0] = aA[(ib + g    ) * 68 + a0 + tc];
            af[1] = aA[(ib + g + 8) * 68 + a0 + tc];
            af[2] = aA[(ib + g    ) * 68 + a0 + tc + 4];
            af[3] = aA[(ib + g + 8) * 68 + a0 + tc + 4];
        }
        #pragma unroll
        for (int nf = 0; nf < 8; nf++) {
            int j = jb + nf * 8 + g;
            unsigned bfr[2] = { kbu[j * 68 + a0 + tc], kbu[j * 68 + a0 + tc + 4] };
            mma_tf32(acc[nf], af, bfr);
        }
    }

    // softmax: rows ib+g (c0,c1) and ib+8+g (c2,c3), half-width (64 cols) per warp
    float mx0 = -1e30f, mx1 = -1e30f;
    #pragma unroll
    for (int nf = 0; nf < 8; nf++) {
        mx0 = fmaxf(mx0, fmaxf(acc[nf][0], acc[nf][1]));
        mx1 = fmaxf(mx1, fmaxf(acc[nf][2], acc[nf][3]));
    }
    mx0 = fmaxf(mx0, __shfl_xor_sync(0xffffffffu, mx0, 1));
    mx0 = fmaxf(mx0, __shfl_xor_sync(0xffffffffu, mx0, 2));
    mx1 = fmaxf(mx1, __shfl_xor_sync(0xffffffffu, mx1, 1));
    mx1 = fmaxf(mx1, __shfl_xor_sync(0xffffffffu, mx1, 2));
    float s0 = 0.f, s1 = 0.f;
    #pragma unroll
    for (int nf = 0; nf < 8; nf++) {
        acc[nf][0] = __expf(acc[nf][0] - mx0); s0 += acc[nf][0];
        acc[nf][1] = __expf(acc[nf][1] - mx0); s0 += acc[nf][1];
        acc[nf][2] = __expf(acc[nf][2] - mx1); s1 += acc[nf][2];
        acc[nf][3] = __expf(acc[nf][3] - mx1); s1 += acc[nf][3];
    }
    s0 += __shfl_xor_sync(0xffffffffu, s0, 1);
    s0 += __shfl_xor_sync(0xffffffffu, s0, 2);
    s1 += __shfl_xor_sync(0xffffffffu, s1, 1);
    s1 += __shfl_xor_sync(0xffffffffu, s1, 2);

    int row0 = ib + g, row1 = row0 + 8;
    if (tc == 0) {
        pm[row0 * 2 + wc2] = make_float2(mx0, s0);
        pm[row1 * 2 + wc2] = make_float2(mx1, s1);
    }
    __syncthreads();
    float2 q0 = pm[row0 * 2 + (wc2 ^ 1)];
    float2 q1 = pm[row1 * 2 + (wc2 ^ 1)];
    float M0 = fmaxf(mx0, q0.x);
    float M1 = fmaxf(mx1, q1.x);
    float f0 = __expf(mx0 - M0) / (s0 * __expf(mx0 - M0) + q0.y * __expf(q0.x - M0));
    float f1 = __expf(mx1 - M1) / (s1 * __expf(mx1 - M1) + q1.y * __expf(q1.x - M1));

    #pragma unroll
    for (int nf = 0; nf < 8; nf++) {
        ebu[row0 * 68 + jb2 + nf * 4 + tc] = bf2pack(acc[nf][0] * f0, acc[nf][1] * f0);
        ebu[row1 * 68 + jb2 + nf * 4 + tc] = bf2pack(acc[nf][2] * f1, acc[nf][3] * f1);
    }
}

// AV (bf16): probs ebu[128][68], V chunk vbu[128][68]; bf16x2 output writes
__device__ __forceinline__ void av_mma(const unsigned* ebu, const unsigned* vbu,
                                       unsigned* outu, int mglob0, int ib, int mb,
                                       int g, int tc) {
    float acc[2][4][4];
    #pragma unroll
    for (int mf = 0; mf < 2; mf++)
        #pragma unroll
        for (int nf = 0; nf < 4; nf++)
            #pragma unroll
            for (int r = 0; r < 4; r++) acc[mf][nf][r] = 0.f;

    #pragma unroll
    for (int j0 = 0; j0 < 128; j0 += 16) {
        int u0 = j0 >> 1;
        unsigned af[2][4];
        #pragma unroll
        for (int mf = 0; mf < 2; mf++) {
            int r0 = ib + mf * 16 + g;
            af[mf][0] = ebu[(r0    ) * 68 + u0 + tc];
            af[mf][1] = ebu[(r0 + 8) * 68 + u0 + tc];
            af[mf][2] = ebu[(r0    ) * 68 + u0 + tc + 4];
            af[mf][3] = ebu[(r0 + 8) * 68 + u0 + tc + 4];
        }
        unsigned bfr[4][2];
        #pragma unroll
        for (int nf = 0; nf < 4; nf++) {
            int m = mb + nf * 8 + g;
            bfr[nf][0] = vbu[m * 68 + u0 + tc];
            bfr[nf][1] = vbu[m * 68 + u0 + tc + 4];
        }
        #pragma unroll
        for (int mf = 0; mf < 2; mf++)
            #pragma unroll
            for (int nf = 0; nf < 4; nf++)
                mma_bf16(acc[mf][nf], af[mf], bfr[nf]);
    }
    #pragma unroll
    for (int mf = 0; mf < 2; mf++) {
        int i = ib + mf * 16 + g;
        #pragma unroll
        for (int nf = 0; nf < 4; nf++) {
            int m = mglob0 + mb + nf * 8 + 2 * tc;
            outu[(size_t)i * (CC / 2) + (m >> 1)]       = bf2pack(acc[mf][nf][0], acc[mf][nf][1]);
            outu[(size_t)(i + 8) * (CC / 2) + (m >> 1)] = bf2pack(acc[mf][nf][2], acc[mf][nf][3]);
    }
    }
}

__device__ __forceinline__ void issue_vchunk(unsigned* dst, const unsigned* vrow, int mc, int tid) {
    #pragma unroll
    for (int k = 0; k < 4; k++) {
        int lin = k * 512 + tid;
        int ml = lin >> 4, seg = lin & 15;
        cpa16(&dst[ml * 68 + seg * 4], vrow + (size_t)(mc + ml) * (NP / 2) + seg * 4);
    }
}

// ---------------- kernel 4: horizontal attention ----------------
__global__ __launch_bounds__(512) void h_attn() {
    int bh = blockIdx.x;
    int b = bh >> 7, h = bh & 127;
    extern __shared__ unsigned smu[];
    unsigned* vb0 = smu;                             // [128][68]
    unsigned* vb1 = smu + 8704;
    unsigned* ebu = smu + 17408;                     // [128][68]
    float2*   pm  = (float2*)(smu + 26112);          // 256 float2
    float*    qs  = (float*)(smu + 26624);           // [64][136]
    float*    kb  = (float*)(smu + 35328);           // [128][68]

    int tid = threadIdx.x;
    int wid = tid >> 5, lane = tid & 31;
    int g = lane >> 2, tc = lane & 3;

    const unsigned* vrow = g_v + (size_t)b * CC * (NP / 2) + h * (WW / 2);
    issue_vchunk(vb0, vrow, 0, tid);
    asm volatile("cp.async.commit_group;");
    issue_vchunk(vb1, vrow, 128, tid);
    asm volatile("cp.async.commit_group;");

    const float* qbase = g_qkv + (size_t)b * 128 * NP + h * WW;
    const float* kbase = qbase + (size_t)64 * NP;
    for (int idx = tid; idx < CQn * WW; idx += 512) {
        int a = idx >> 7, i = idx & 127;
        qs[a * 136 + i] = f2tff(qbase[(size_t)a * NP + i]);
    }
    for (int idx = tid; idx < CQn * WW; idx += 512) {
        int c2 = idx >> 7, w2 = idx & 127;
        kb[(((w2 & 1) << 6) + c2) * 68 + (w2 >> 1)] = f2tff(kbase[(size_t)c2 * NP + w2]);
    }
    __syncthreads();

    energy_softmax<1>((const unsigned*)qs, (const unsigned*)kb, ebu, pm, wid, lane);
    __syncthreads();

    unsigned* chu = g_ch + (size_t)bh * WW * (CC / 2);
    int ib4 = (wid >> 2) * 32, mb4 = (wid & 3) * 32;
    for (int c = 0; c < 4; c++) {
        if (c == 3) asm volatile("cp.async.wait_group 0;");
        else        asm volatile("cp.async.wait_group 1;");
        __syncthreads();
        av_mma(ebu, (c & 1) ? vb1 : vb0, chu, c * 128, ib4, mb4, g, tc);
        __syncthreads();
        if (c < 2) {
            issue_vchunk((c & 1) ? vb1 : vb0, vrow, (c + 2) * 128, tid);
            asm volatile("cp.async.commit_group;");
        }
    }
}

// ---------------- kernel 5: vertical attention ----------------
__global__ __launch_bounds__(512) void v_attn() {
    int bw = blockIdx.x;
    int b = bw >> 7, w = bw & 127;
    extern __shared__ unsigned smu[];
    unsigned* ebu = smu;                             // [128][68]
    float2*   pm  = (float2*)(smu + 8704);           // 256 float2
    float*    aq  = (float*)(smu + 9216);            // [128][68]
    float*    kb  = (float*)(smu + 17920);           // [128][68]
    unsigned* vbu = smu + 9216;                      // [128][68] (aliases aq after energy)

    int tid = threadIdx.x;
    int wid = tid >> 5, lane = tid & 31;
    int g = lane >> 2, tc = lane & 3;

    const float* qbaseT = g_qkvT + (size_t)b * 128 * NP + w * HH;
    const float* kbaseT = qbaseT + (size_t)64 * NP;
    for (int idx = tid; idx < HH * CQn; idx += 512) {
        int i = idx >> 6, a = idx & 63;
        aq[i * 68 + a] = f2tff(qbaseT[(size_t)(i >> 1) * NP + ((i & 1) << 6) + a]);
    }
    for (int idx = tid; idx < CQn * HH; idx += 512) {
        int a = idx >> 7, j = idx & 127;
        kb[j * 68 + a] = f2tff(kbaseT[(size_t)a * NP + j]);
    }
    __syncthreads();

    energy_softmax<0>((const unsigned*)aq, (const unsigned*)kb, ebu, pm, wid, lane);
    __syncthreads();

    const unsigned* vTu = g_vT + (size_t)b * CC * (NP / 2) + w * (HH / 2);
    unsigned* cvu = g_cv + (size_t)bw * HH * (CC / 2);
    int ib4 = (wid >> 2) * 32, mb4 = (wid & 3) * 32;

    // register-pipelined V gather/pack: chunk c covers channels 128c..128c+127 (t=c)
    int u_base = tid & 3, p2 = (tid >> 2) & 63, upper = tid >> 8;
    unsigned r[16];

    #pragma unroll
    for (int k = 0; k < 8; k++) {                    // load chunk 0
        int u = u_base + 4 * (2 * k + upper);
        unsigned lo2 = vTu[(size_t)(8 * u + 0) * (NP / 2) + p2];
        unsigned hi2 = vTu[(size_t)(8 * u + 4) * (NP / 2) + p2];
        r[2 * k]     = __byte_perm(lo2, hi2, 0x5410);
        r[2 * k + 1] = __byte_perm(lo2, hi2, 0x7632);
    }

    for (int c = 0; c < 4; c++) {
        #pragma unroll
        for (int k = 0; k < 8; k++) {
            int u = u_base + 4 * (2 * k + upper);
            vbu[(2 * p2    ) * 68 + u] = r[2 * k];
            vbu[(2 * p2 + 1) * 68 + u] = r[2 * k + 1];
        }
        __syncthreads();
        if (c < 3) {
            #pragma unroll
            for (int k = 0; k < 8; k++) {            // prefetch chunk c+1 into regs
                int u = u_base + 4 * (2 * k + upper);
                unsigned lo2 = vTu[(size_t)(8 * u + c + 1) * (NP / 2) + p2];
                unsigned hi2 = vTu[(size_t)(8 * u + 4 + c + 1) * (NP / 2) + p2];
                r[2 * k]     = __byte_perm(lo2, hi2, 0x5410);
                r[2 * k + 1] = __byte_perm(lo2, hi2, 0x7632);
            }
        }
        av_mma(ebu, vbu, cvu, c * 128, ib4, mb4, g, tc);
        __syncthreads();
    }
}

// ---------------- kernel 6: combine ----------------
// out[b][c][h][w] = gamma*(ch[bh][w][c] + cv[bw][h][c]) + x[b][c][h][w], ch/cv bf16
__global__ __launch_bounds__(256) void combine_kernel(const float* __restrict__ x,
                                                      const float* __restrict__ gamma,
                                                      float* __restrict__ out) {
    __shared__ float tb[32][67];
    int w0 = blockIdx.x * 32;
    int c0 = blockIdx.y * 64;
    int bh = blockIdx.z;
    int b = bh >> 7, h = bh & 127;
    int tx = threadIdx.x, ty = threadIdx.y;

    for (int r = ty; r < 32; r += 8) {
        int w = w0 + r;
        unsigned chp = g_ch[((size_t)bh * WW + w) * (CC / 2) + (c0 >> 1) + tx];
        unsigned cvp = g_cv[(((size_t)(b * WW + w)) * HH + h) * (CC / 2) + (c0 >> 1) + tx];
        float lo = __uint_as_float(chp << 16) + __uint_as_float(cvp << 16);
        float hi = __uint_as_float(chp & 0xffff0000u) + __uint_as_float(cvp & 0xffff0000u);
        tb[r][2 * tx]     = lo;
        tb[r][2 * tx + 1] = hi;
    }
    __syncthreads();
    float gv = gamma[0];
    for (int rr = ty; rr < 64; rr += 8) {
        int c = c0 + rr;
        size_t o = ((size_t)(b * CC + c) * HH + h) * WW + w0 + tx;
        out[o] = gv * tb[tx][rr] + x[o];
    }
}

// ---------------- launch ----------------
extern "C" void kernel_launch(void* const* d_in, const int* in_sizes, int n_in,
                              void* d_out, int out_size) {
    const float* x     = (const float*)d_in[0];
    const float* Wq    = (const float*)d_in[1];
    const float* bq    = (const float*)d_in[2];
    const float* Wk    = (const float*)d_in[3];
    const float* bk    = (const float*)d_in[4];
    const float* Wv    = (const float*)d_in[5];
    const float* bv    = (const float*)d_in[6];
    const float* gamma = (const float*)d_in[7];
    float* out = (float*)d_out;

    const int HSM = 44032 * 4;   // 176128 B
    const int VSM = 26624 * 4;   // 106496 B
    cudaFuncSetAttribute(h_attn, cudaFuncAttributeMaxDynamicSharedMemorySize, HSM);
    cudaFuncSetAttribute(v_attn, cudaFuncAttributeMaxDynamicSharedMemorySize, VSM);

    pack_kernel<<<(CO * CC + 255) / 256, 256>>>(Wq, bq, Wk, bk, Wv, bv);
    qkv_gemm<<<dim3(5, 128, 4), 256>>>(x);
    transpose_qk<<<dim3(4, 4, BB * 128), dim3(32, 8, 1)>>>();
    transpose_v<<<dim3(2, 2, BB * CC), 256>>>();
    h_attn<<<BB * HH, 512, HSM>>>();
    v_attn<<<BB * WW, 512, VSM>>>();
    combine_kernel<<<dim3(WW / 32, CC / 64, BB * HH), dim3(32, 8, 1)>>>(x, gamma, out);
}

// round 5
// speedup vs baseline: 4.0424x; 1.1439x over previous
#include <cuda_runtime.h>

#define CC 512
#define CQn 64
#define HH 128
#define WW 128
#define BB 4
#define CO 640
#define NP (HH*WW)

// ---------------- scratch ----------------
__device__ __align__(256) float    g_qkv [(size_t)BB*128*NP];      // (b, o<128, h, w) f32: q 0..63, k 64..127
__device__ __align__(256) float    g_qkvT[(size_t)BB*128*NP];      // (b, o<128, w, h)
__device__ __align__(256) unsigned g_v   [(size_t)BB*CC*NP/2];     // (b, o, h, w) bf16 pairs along w
__device__ __align__(256) unsigned g_vT  [(size_t)BB*CC*NP/2];     // (b, o, w, h) bf16 pairs along h
__device__ __align__(256) unsigned g_ch  [(size_t)BB*HH*WW*CC/2];  // [bh][w][c] bf16
__device__ __align__(256) unsigned g_cv  [(size_t)BB*WW*HH*CC/2];  // [bw][h][c] bf16
__device__ float    g_Wqk[128*CC];        // q,k weights, tf32-rounded f32
__device__ unsigned g_Wv [CC*CC/2];       // V weights bf16, pairs along k
__device__ float    g_ball[CO];

// ---------------- helpers ----------------
__device__ __forceinline__ float f2tff(float f) {
    unsigned u; asm("cvt.rna.tf32.f32 %0, %1;" : "=r"(u) : "f"(f)); return __uint_as_float(u);
}
__device__ __forceinline__ unsigned bf2pack(float lo, float hi) {
    unsigned r; asm("cvt.rn.bf16x2.f32 %0, %1, %2;" : "=r"(r) : "f"(hi), "f"(lo)); return r;
}
__device__ __forceinline__ void mma_tf32(float c[4], const unsigned a[4], const unsigned b[2]) {
    asm volatile("mma.sync.aligned.m16n8k8.row.col.f32.tf32.tf32.f32 "
        "{%0,%1,%2,%3}, {%4,%5,%6,%7}, {%8,%9}, {%0,%1,%2,%3};"
        : "+f"(c[0]), "+f"(c[1]), "+f"(c[2]), "+f"(c[3])
        : "r"(a[0]), "r"(a[1]), "r"(a[2]), "r"(a[3]), "r"(b[0]), "r"(b[1]));
}
__device__ __forceinline__ void mma_bf16(float c[4], const unsigned a[4], const unsigned b[2]) {
    asm volatile("mma.sync.aligned.m16n8k16.row.col.f32.bf16.bf16.f32 "
        "{%0,%1,%2,%3}, {%4,%5,%6,%7}, {%8,%9}, {%0,%1,%2,%3};"
        : "+f"(c[0]), "+f"(c[1]), "+f"(c[2]), "+f"(c[3])
        : "r"(a[0]), "r"(a[1]), "r"(a[2]), "r"(a[3]), "r"(b[0]), "r"(b[1]));
}
__device__ __forceinline__ void cpa16(void* dst, const void* src) {
    unsigned d = (unsigned)__cvta_generic_to_shared(dst);
    asm volatile("cp.async.ca.shared.global [%0], [%1], 16;" :: "r"(d), "l"(src));
}

// ---------------- kernel 1: pack weights ----------------
__global__ void pack_kernel(const float* __restrict__ Wq, const float* __restrict__ bq,
                            const float* __restrict__ Wk, const float* __restrict__ bk,
                            const float* __restrict__ Wv, const float* __restrict__ bv) {
    int idx = blockIdx.x * blockDim.x + threadIdx.x;
    if (idx < 128 * CC) {
        int o = idx / CC, c = idx % CC;
        g_Wqk[idx] = f2tff(o < CQn ? Wq[o * CC + c] : Wk[(o - CQn) * CC + c]);
    }
    if (idx < CC * CC / 2) {
        int o = idx / (CC / 2), kp = idx % (CC / 2);
        g_Wv[idx] = bf2pack(Wv[o * CC + 2 * kp], Wv[o * CC + 2 * kp + 1]);
    }
    if (idx < CO)
        g_ball[idx] = (idx < CQn) ? bq[idx] : (idx < 2 * CQn) ? bk[idx - CQn] : bv[idx - 2 * CQn];
}

// ---------------- kernel 2a: Q/K GEMM (tf32, cp.async double-buffered) ----------------
__global__ __launch_bounds__(256) void qk_gemm(const float* __restrict__ x) {
    __shared__ float As[2][128 * 20];
    __shared__ float Bs[2][16 * 136];

    int n0 = blockIdx.x * 128;
    int b  = blockIdx.y;

    const float* A = g_Wqk;
    const float* B = x + (size_t)b * CC * NP;
    float*       Cp = g_qkv + (size_t)b * 128 * NP;

    int tid = threadIdx.x;
    int wid = tid >> 5, lane = tid & 31;
    int wm = wid >> 1, wn = wid & 1;
    int g = lane >> 2, tc = lane & 3;

    int arow = tid >> 2, acol = (tid & 3) * 4;
    int brow = tid >> 5, bcol = lane * 4;

    float acc[2][8][4];
    #pragma unroll
    for (int mf = 0; mf < 2; mf++)
        #pragma unroll
        for (int nf = 0; nf < 8; nf++)
            #pragma unroll
            for (int r = 0; r < 4; r++) acc[mf][nf][r] = 0.f;

    #pragma unroll
    for (int h = 0; h < 2; h++) {
        cpa16(&As[0][(arow + h * 64) * 20 + acol], &A[(size_t)(arow + h * 64) * CC + acol]);
        cpa16(&Bs[0][(brow + h * 8) * 136 + bcol], &B[(size_t)(brow + h * 8) * NP + n0 + bcol]);
    }
    asm volatile("cp.async.commit_group;");
    asm volatile("cp.async.wait_group 0;");
    __syncthreads();

    for (int k0 = 0; k0 < CC; k0 += 16) {
        int buf = (k0 >> 4) & 1;
        if (k0 + 16 < CC) {
            #pragma unroll
            for (int h = 0; h < 2; h++) {
                cpa16(&As[buf ^ 1][(arow + h * 64) * 20 + acol],
                      &A[(size_t)(arow + h * 64) * CC + k0 + 16 + acol]);
                cpa16(&Bs[buf ^ 1][(brow + h * 8) * 136 + bcol],
                      &B[(size_t)(k0 + 16 + brow + h * 8) * NP + n0 + bcol]);
            }
            asm volatile("cp.async.commit_group;");
        }
        const unsigned* Asu = (const unsigned*)As[buf];
        const unsigned* Bsu = (const unsigned*)Bs[buf];
        #pragma unroll
        for (int ks = 0; ks < 16; ks += 8) {
            unsigned af[2][4];
            #pragma unroll
            for (int mf = 0; mf < 2; mf++) {
                int r0 = wm * 32 + mf * 16 + g;
                af[mf][0] = Asu[(r0    ) * 20 + ks + tc];
                af[mf][1] = Asu[(r0 + 8) * 20 + ks + tc];
                af[mf][2] = Asu[(r0    ) * 20 + ks + tc + 4];
                af[mf][3] = Asu[(r0 + 8) * 20 + ks + tc + 4];
            }
            unsigned bfv[8][2];
            #pragma unroll
            for (int nf = 0; nf < 8; nf++) {
                int nn = wn * 64 + nf * 8 + g;
                bfv[nf][0] = Bsu[(ks + tc    ) * 136 + nn];
                bfv[nf][1] = Bsu[(ks + tc + 4) * 136 + nn];
            }
            #pragma unroll
            for (int mf = 0; mf < 2; mf++)
                #pragma unroll
                for (int nf = 0; nf < 8; nf++)
                    mma_tf32(acc[mf][nf], af[mf], bfv[nf]);
        }
        if (k0 + 16 < CC) asm volatile("cp.async.wait_group 0;");
        __syncthreads();
    }

    #pragma unroll
    for (int mf = 0; mf < 2; mf++) {
        int i0 = wm * 32 + mf * 16 + g;
        float bv0 = g_ball[i0], bv1 = g_ball[i0 + 8];
        #pragma unroll
        for (int nf = 0; nf < 8; nf++) {
            int j = n0 + wn * 64 + nf * 8 + 2 * tc;
            float2 w0 = {acc[mf][nf][0] + bv0, acc[mf][nf][1] + bv0};
            float2 w1 = {acc[mf][nf][2] + bv1, acc[mf][nf][3] + bv1};
            *reinterpret_cast<float2*>(&Cp[(size_t)i0 * NP + j])       = w0;
            *reinterpret_cast<float2*>(&Cp[(size_t)(i0 + 8) * NP + j]) = w1;
        }
    }
}

// ---------------- kernel 2b: V GEMM (bf16 m16n8k16) ----------------
// A = g_Wv [512][256 u32] via cp.async; B = x f32 packed to bf16 in registers.
__global__ __launch_bounds__(256) void v_gemm(const float* __restrict__ x) {
    __shared__ unsigned As[2][128 * 20];   // [m][ku], ku 0..15 per 32-K tile
    __shared__ unsigned Bs[2][128 * 20];   // [n][ku]

    int m0 = blockIdx.x * 128;
    int n0 = blockIdx.y * 128;
    int b  = blockIdx.z;

    const unsigned* A = g_Wv;
    const float*    B = x + (size_t)b * CC * NP;
    unsigned*       vp = g_v + (size_t)b * CC * (NP / 2);

    int tid = threadIdx.x;
    int wid = tid >> 5, lane = tid & 31;
    int wm = wid >> 1, wn = wid & 1;
    int g = lane >> 2, tc = lane & 3;

    // A staging: row = tid>>1 (0..127), two 16B chunks at cols (tid&1)*8, +4
    int ar = tid >> 1, ac = (tid & 1) * 8;
    // B staging: wk = tid>>5, nl = lane; ku0 = (wk&3)*4, nbase = 64*(wk>>2)
    int ku0 = (wid & 3) * 4, nbase = 64 * (wid >> 2);

    float rB[2][8];
    #pragma unroll
    for (int r = 0; r < 2; r++) {
        int n = nbase + 32 * r + lane;
        #pragma unroll
        for (int d = 0; d < 8; d++)
            rB[r][d] = B[(size_t)(2 * ku0 + d) * NP + n0 + n];
    }
    #pragma unroll
    for (int c = 0; c < 2; c++)
        cpa16(&As[0][ar * 20 + ac + 4 * c], &A[(size_t)(m0 + ar) * 256 + ac + 4 * c]);
    asm volatile("cp.async.commit_group;");
    #pragma unroll
    for (int r = 0; r < 2; r++) {
        int n = nbase + 32 * r + lane;
        unsigned p[4];
        #pragma unroll
        for (int d = 0; d < 4; d++) p[d] = bf2pack(rB[r][2 * d], rB[r][2 * d + 1]);
        *reinterpret_cast<uint4*>(&Bs[0][n * 20 + ku0]) = *reinterpret_cast<uint4*>(p);
    }
    asm volatile("cp.async.wait_group 0;");
    __syncthreads();

    float acc[2][8][4];
    #pragma unroll
    for (int mf = 0; mf < 2; mf++)
        #pragma unroll
        for (int nf = 0; nf < 8; nf++)
            #pragma unroll
            for (int r = 0; r < 4; r++) acc[mf][nf][r] = 0.f;

    for (int kt = 0; kt < 16; kt++) {
        int buf = kt & 1;
        int k0n = (kt + 1) * 32;
        if (kt < 15) {
            #pragma unroll
            for (int c = 0; c < 2; c++)
                cpa16(&As[buf ^ 1][ar * 20 + ac + 4 * c],
                      &A[(size_t)(m0 + ar) * 256 + (k0n >> 1) + ac + 4 * c]);
            asm volatile("cp.async.commit_group;");
            #pragma unroll
            for (int r = 0; r < 2; r++) {
                int n = nbase + 32 * r + lane;
                #pragma unroll
                for (int d = 0; d < 8; d++)
                    rB[r][d] = B[(size_t)(k0n + 2 * ku0 + d) * NP + n0 + n];
            }
        }

        const unsigned* Asu = As[buf];
        const unsigned* Bsu = Bs[buf];
        #pragma unroll
        for (int s = 0; s < 2; s++) {
            int s8 = s * 8;
            unsigned af[2][4];
            #pragma unroll
            for (int mf = 0; mf < 2; mf++) {
                int r0 = wm * 32 + mf * 16 + g;
                af[mf][0] = Asu[(r0    ) * 20 + s8 + tc];
                af[mf][1] = Asu[(r0 + 8) * 20 + s8 + tc];
                af[mf][2] = Asu[(r0    ) * 20 + s8 + tc + 4];
                af[mf][3] = Asu[(r0 + 8) * 20 + s8 + tc + 4];
            }
            unsigned bfv[8][2];
            #pragma unroll
            for (int nf = 0; nf < 8; nf++) {
                int nn = wn * 64 + nf * 8 + g;
                bfv[nf][0] = Bsu[nn * 20 + s8 + tc];
                bfv[nf][1] = Bsu[nn * 20 + s8 + tc + 4];
            }
            #pragma unroll
            for (int mf = 0; mf < 2; mf++)
                #pragma unroll
                for (int nf = 0; nf < 8; nf++)
                    mma_bf16(acc[mf][nf], af[mf], bfv[nf]);
        }

        if (kt < 15) {
            #pragma unroll
            for (int r = 0; r < 2; r++) {
                int n = nbase + 32 * r + lane;
                unsigned p[4];
                #pragma unroll
                for (int d = 0; d < 4; d++) p[d] = bf2pack(rB[r][2 * d], rB[r][2 * d + 1]);
                *reinterpret_cast<uint4*>(&Bs[buf ^ 1][n * 20 + ku0]) = *reinterpret_cast<uint4*>(p);
            }
            asm volatile("cp.async.wait_group 0;");
        }
        __syncthreads();
    }

    #pragma unroll
    for (int mf = 0; mf < 2; mf++) {
        int i0 = m0 + wm * 32 + mf * 16 + g;
        float bv0 = g_ball[128 + i0], bv1 = g_ball[128 + i0 + 8];
        #pragma unroll
        for (int nf = 0; nf < 8; nf++) {
            int j = n0 + wn * 64 + nf * 8 + 2 * tc;
            vp[(size_t)i0 * (NP / 2) + (j >> 1)]       = bf2pack(acc[mf][nf][0] + bv0, acc[mf][nf][1] + bv0);
            vp[(size_t)(i0 + 8) * (NP / 2) + (j >> 1)] = bf2pack(acc[mf][nf][2] + bv1, acc[mf][nf][3] + bv1);
        }
    }
}

// ---------------- kernel 3a: f32 (H,W) transpose for q,k planes ----------------
__global__ __launch_bounds__(256) void transpose_qk() {
    __shared__ float t[32][33];
    int plane = blockIdx.z;
    const float* src = g_qkv + (size_t)plane * NP;
    float*       dst = g_qkvT + (size_t)plane * NP;
    int w0 = blockIdx.x * 32, h0 = blockIdx.y * 32;
    int tx = threadIdx.x, ty = threadIdx.y;
    #pragma unroll
    for (int r = 0; r < 32; r += 8)
        t[ty + r][tx] = src[(size_t)(h0 + ty + r) * WW + w0 + tx];
    __syncthreads();
    #pragma unroll
    for (int r = 0; r < 32; r += 8)
        dst[(size_t)(w0 + ty + r) * HH + h0 + tx] = t[tx][ty + r];
}

// ---------------- kernel 3b: bf16 (H,W) transpose for V planes ----------------
__global__ __launch_bounds__(256) void transpose_v() {
    __shared__ unsigned t[64][33];
    int plane = blockIdx.z;
    const unsigned* src = g_v + (size_t)plane * (NP / 2);
    unsigned*       dst = g_vT + (size_t)plane * (NP / 2);
    int h0 = blockIdx.y * 64, w0 = blockIdx.x * 64;
    int tx = threadIdx.x & 31, ty = threadIdx.x >> 5;
    #pragma unroll
    for (int h = ty; h < 64; h += 8)
        t[h][tx] = src[(size_t)(h0 + h) * 64 + (w0 >> 1) + tx];
    __syncthreads();
    #pragma unroll
    for (int w = ty; w < 64; w += 8) {
        unsigned a = t[2 * tx][w >> 1], b = t[2 * tx + 1][w >> 1];
        unsigned r = (w & 1) ? __byte_perm(a, b, 0x7632) : __byte_perm(a, b, 0x5410);
        dst[(size_t)(w0 + w) * 64 + (h0 >> 1) + tx] = r;
    }
}

// =============== attention machinery (512 threads, 16 warps) ===============

template<int AKMAJOR>
__device__ __forceinline__ void energy_softmax(const unsigned* aA, const unsigned* kbu,
                                               unsigned* ebu, float2* pm, int wid, int lane) {
    int wr8 = wid >> 1, wc2 = wid & 1;
    int ib = wr8 * 16, jb = wc2 * 64, jb2 = wc2 * 32;
    int g = lane >> 2, tc = lane & 3;

    float acc[8][4];
    #pragma unroll
    for (int nf = 0; nf < 8; nf++)
        #pragma unroll
        for (int r = 0; r < 4; r++) acc[nf][r] = 0.f;

    for (int a0 = 0; a0 < 64; a0 += 8) {
        unsigned af[4];
        if (AKMAJOR) {
            af[0] = aA[(a0 + tc    ) * 136 + ib + g];
            af[1] = aA[(a0 + tc    ) * 136 + ib + g + 8];
            af[2] = aA[(a0 + tc + 4) * 136 + ib + g];
            af[3] = aA[(a0 + tc + 4) * 136 + ib + g + 8];
        } else {
            af[0] = aA[(ib + g    ) * 68 + a0 + tc];
            af[1] = aA[(ib + g + 8) * 68 + a0 + tc];
            af[2] = aA[(ib + g    ) * 68 + a0 + tc + 4];
            af[3] = aA[(ib + g + 8) * 68 + a0 + tc + 4];
        }
        #pragma unroll
        for (int nf = 0; nf < 8; nf++) {
            int j = jb + nf * 8 + g;
            unsigned bfr[2] = { kbu[j * 68 + a0 + tc], kbu[j * 68 + a0 + tc + 4] };
            mma_tf32(acc[nf], af, bfr);
        }
    }

    float mx0 = -1e30f, mx1 = -1e30f;
    #pragma unroll
    for (int nf = 0; nf < 8; nf++) {
        mx0 = fmaxf(mx0, fmaxf(acc[nf][0], acc[nf][1]));
        mx1 = fmaxf(mx1, fmaxf(acc[nf][2], acc[nf][3]));
    }
    mx0 = fmaxf(mx0, __shfl_xor_sync(0xffffffffu, mx0, 1));
    mx0 = fmaxf(mx0, __shfl_xor_sync(0xffffffffu, mx0, 2));
    mx1 = fmaxf(mx1, __shfl_xor_sync(0xffffffffu, mx1, 1));
    mx1 = fmaxf(mx1, __shfl_xor_sync(0xffffffffu, mx1, 2));
    float s0 = 0.f, s1 = 0.f;
    #pragma unroll
    for (int nf = 0; nf < 8; nf++) {
        acc[nf][0] = __expf(acc[nf][0] - mx0); s0 += acc[nf][0];
        acc[nf][1] = __expf(acc[nf][1] - mx0); s0 += acc[nf][1];
        acc[nf][2] = __expf(acc[nf][2] - mx1); s1 += acc[nf][2];
        acc[nf][3] = __expf(acc[nf][3] - mx1); s1 += acc[nf][3];
    }
    s0 += __shfl_xor_sync(0xffffffffu, s0, 1);
    s0 += __shfl_xor_sync(0xffffffffu, s0, 2);
    s1 += __shfl_xor_sync(0xffffffffu, s1, 1);
    s1 += __shfl_xor_sync(0xffffffffu, s1, 2);

    int row0 = ib + g, row1 = row0 + 8;
    if (tc == 0) {
        pm[row0 * 2 + wc2] = make_float2(mx0, s0);
        pm[row1 * 2 + wc2] = make_float2(mx1, s1);
    }
    __syncthreads();
    float2 q0 = pm[row0 * 2 + (wc2 ^ 1)];
    float2 q1 = pm[row1 * 2 + (wc2 ^ 1)];
    float M0 = fmaxf(mx0, q0.x);
    float M1 = fmaxf(mx1, q1.x);
    float f0 = __expf(mx0 - M0) / (s0 * __expf(mx0 - M0) + q0.y * __expf(q0.x - M0));
    float f1 = __expf(mx1 - M1) / (s1 * __expf(mx1 - M1) + q1.y * __expf(q1.x - M1));

    #pragma unroll
    for (int nf = 0; nf < 8; nf++) {
        ebu[row0 * 68 + jb2 + nf * 4 + tc] = bf2pack(acc[nf][0] * f0, acc[nf][1] * f0);
        ebu[row1 * 68 + jb2 + nf * 4 + tc] = bf2pack(acc[nf][2] * f1, acc[nf][3] * f1);
    }
}

__device__ __forceinline__ void av_mma(const unsigned* ebu, const unsigned* vbu,
                                       unsigned* outu, int mglob0, int ib, int mb,
                                       int g, int tc) {
    float acc[2][4][4];
    #pragma unroll
    for (int mf = 0; mf < 2; mf++)
        #pragma unroll
        for (int nf = 0; nf < 4; nf++)
            #pragma unroll
            for (int r = 0; r < 4; r++) acc[mf][nf][r] = 0.f;

    #pragma unroll
    for (int j0 = 0; j0 < 128; j0 += 16) {
        int u0 = j0 >> 1;
        unsigned af[2][4];
        #pragma unroll
        for (int mf = 0; mf < 2; mf++) {
            int r0 = ib + mf * 16 + g;
            af[mf][0] = ebu[(r0    ) * 68 + u0 + tc];
            af[mf][1] = ebu[(r0 + 8) * 68 + u0 + tc];
            af[mf][2] = ebu[(r0    ) * 68 + u0 + tc + 4];
            af[mf][3] = ebu[(r0 + 8) * 68 + u0 + tc + 4];
        }
        unsigned bfr[4][2];
        #pragma unroll
        for (int nf = 0; nf < 4; nf++) {
            int m = mb + nf * 8 + g;
            bfr[nf][0] = vbu[m * 68 + u0 + tc];
            bfr[nf][1] = vbu[m * 68 + u0 + tc + 4];
        }
        #pragma unroll
        for (int mf = 0; mf < 2; mf++)
            #pragma unroll
            for (int nf = 0; nf < 4; nf++)
                mma_bf16(acc[mf][nf], af[mf], bfr[nf]);
    }
    #pragma unroll
    for (int mf = 0; mf < 2; mf++) {
        int i = ib + mf * 16 + g;
        #pragma unroll
        for (int nf = 0; nf < 4; nf++) {
            int m = mglob0 + mb + nf * 8 + 2 * tc;
            outu[(size_t)i * (CC / 2) + (m >> 1)]       = bf2pack(acc[mf][nf][0], acc[mf][nf][1]);
            outu[(size_t)(i + 8) * (CC / 2) + (m >> 1)] = bf2pack(acc[mf][nf][2], acc[mf][nf][3]);
        }
    }
}

__device__ __forceinline__ void issue_vchunk(unsigned* dst, const unsigned* vrow, int mc, int tid) {
    #pragma unroll
    for (int k = 0; k < 4; k++) {
        int lin = k * 512 + tid;
        int ml = lin >> 4, seg = lin & 15;
        cpa16(&dst[ml * 68 + seg * 4], vrow + (size_t)(mc + ml) * (NP / 2) + seg * 4);
    }
}

// ---------------- kernel 4: merged attention (blocks 0..511 = h, 512..1023 = v) ----------------
__global__ __launch_bounds__(512) void attn() {
    extern __shared__ unsigned smu[];
    int tid = threadIdx.x;
    int wid = tid >> 5, lane = tid & 31;
    int g = lane >> 2, tc = lane & 3;

    if (blockIdx.x < 512) {
        // -------- horizontal --------
        int bh = blockIdx.x;
        int b = bh >> 7, h = bh & 127;
        unsigned* vb0 = smu;
        unsigned* vb1 = smu + 8704;
        unsigned* ebu = smu + 17408;
        float2*   pm  = (float2*)(smu + 26112);
        float*    qs  = (float*)(smu + 26624);
        float*    kb  = (float*)(smu + 35328);

        const unsigned* vrow = g_v + (size_t)b * CC * (NP / 2) + h * (WW / 2);
        issue_vchunk(vb0, vrow, 0, tid);
        asm volatile("cp.async.commit_group;");
        issue_vchunk(vb1, vrow, 128, tid);
        asm volatile("cp.async.commit_group;");

        const float* qbase = g_qkv + (size_t)b * 128 * NP + h * WW;
        const float* kbase = qbase + (size_t)64 * NP;
        for (int idx = tid; idx < CQn * WW; idx += 512) {
            int a = idx >> 7, i = idx & 127;
            qs[a * 136 + i] = f2tff(qbase[(size_t)a * NP + i]);
        }
        for (int idx = tid; idx < CQn * WW; idx += 512) {
            int c2 = idx >> 7, w2 = idx & 127;
            kb[(((w2 & 1) << 6) + c2) * 68 + (w2 >> 1)] = f2tff(kbase[(size_t)c2 * NP + w2]);
        }
        __syncthreads();

        energy_softmax<1>((const unsigned*)qs, (const unsigned*)kb, ebu, pm, wid, lane);
        __syncthreads();

        unsigned* chu = g_ch + (size_t)bh * WW * (CC / 2);
        int ib4 = (wid >> 2) * 32, mb4 = (wid & 3) * 32;
        for (int c = 0; c < 4; c++) {
            if (c == 3) asm volatile("cp.async.wait_group 0;");
            else        asm volatile("cp.async.wait_group 1;");
            __syncthreads();
            av_mma(ebu, (c & 1) ? vb1 : vb0, chu, c * 128, ib4, mb4, g, tc);
            __syncthreads();
            if (c < 2) {
                issue_vchunk((c & 1) ? vb1 : vb0, vrow, (c + 2) * 128, tid);
                asm volatile("cp.async.commit_group;");
            }
        }
    } else {
        // -------- vertical --------
        int bw = blockIdx.x - 512;
        int b = bw >> 7, w = bw & 127;
        unsigned* ebu = smu;
        float2*   pm  = (float2*)(smu + 8704);
        float*    aq  = (float*)(smu + 9216);
        float*    kb  = (float*)(smu + 17920);
        unsigned* vbu = smu + 9216;

        const float* qbaseT = g_qkvT + (size_t)b * 128 * NP + w * HH;
        const float* kbaseT = qbaseT + (size_t)64 * NP;
        for (int idx = tid; idx < HH * CQn; idx += 512) {
            int i = idx >> 6, a = idx & 63;
            aq[i * 68 + a] = f2tff(qbaseT[(size_t)(i >> 1) * NP + ((i & 1) << 6) + a]);
        }
        for (int idx = tid; idx < CQn * HH; idx += 512) {
            int a = idx >> 7, j = idx & 127;
            kb[j * 68 + a] = f2tff(kbaseT[(size_t)a * NP + j]);
        }
        __syncthreads();

        energy_softmax<0>((const unsigned*)aq, (const unsigned*)kb, ebu, pm, wid, lane);
        __syncthreads();

        const unsigned* vTu = g_vT + (size_t)b * CC * (NP / 2) + w * (HH / 2);
        unsigned* cvu = g_cv + (size_t)bw * HH * (CC / 2);
        int ib4 = (wid >> 2) * 32, mb4 = (wid & 3) * 32;

        int u_base = tid & 3, p2 = (tid >> 2) & 63, upper = tid >> 8;
        unsigned r[16];

        #pragma unroll
        for (int k = 0; k < 8; k++) {
            int u = u_base + 4 * (2 * k + upper);
            unsigned lo2 = vTu[(size_t)(8 * u + 0) * (NP / 2) + p2];
            unsigned hi2 = vTu[(size_t)(8 * u + 4) * (NP / 2) + p2];
            r[2 * k]     = __byte_perm(lo2, hi2, 0x5410);
            r[2 * k + 1] = __byte_perm(lo2, hi2, 0x7632);
        }

        for (int c = 0; c < 4; c++) {
            #pragma unroll
            for (int k = 0; k < 8; k++) {
                int u = u_base + 4 * (2 * k + upper);
                vbu[(2 * p2    ) * 68 + u] = r[2 * k];
                vbu[(2 * p2 + 1) * 68 + u] = r[2 * k + 1];
            }
            __syncthreads();
            if (c < 3) {
                #pragma unroll
                for (int k = 0; k < 8; k++) {
                    int u = u_base + 4 * (2 * k + upper);
                    unsigned lo2 = vTu[(size_t)(8 * u + c + 1) * (NP / 2) + p2];
                    unsigned hi2 = vTu[(size_t)(8 * u + 4 + c + 1) * (NP / 2) + p2];
                    r[2 * k]     = __byte_perm(lo2, hi2, 0x5410);
                    r[2 * k + 1] = __byte_perm(lo2, hi2, 0x7632);
                }
            }
            av_mma(ebu, vbu, cvu, c * 128, ib4, mb4, g, tc);
            __syncthreads();
        }
    }
}

// ---------------- kernel 6: combine ----------------
__global__ __launch_bounds__(256) void combine_kernel(const float* __restrict__ x,
                                                      const float* __restrict__ gamma,
                                                      float* __restrict__ out) {
    __shared__ float tb[32][67];
    int w0 = blockIdx.x * 32;
    int c0 = blockIdx.y * 64;
    int bh = blockIdx.z;
    int b = bh >> 7, h = bh & 127;
    int tx = threadIdx.x, ty = threadIdx.y;

    for (int r = ty; r < 32; r += 8) {
        int w = w0 + r;
        unsigned chp = g_ch[((size_t)bh * WW + w) * (CC / 2) + (c0 >> 1) + tx];
        unsigned cvp = g_cv[(((size_t)(b * WW + w)) * HH + h) * (CC / 2) + (c0 >> 1) + tx];
        float lo = __uint_as_float(chp << 16) + __uint_as_float(cvp << 16);
        float hi = __uint_as_float(chp & 0xffff0000u) + __uint_as_float(cvp & 0xffff0000u);
        tb[r][2 * tx]     = lo;
        tb[r][2 * tx + 1] = hi;
    }
    __syncthreads();
    float gv = gamma[0];
    for (int rr = ty; rr < 64; rr += 8) {
        int c = c0 + rr;
        size_t o = ((size_t)(b * CC + c) * HH + h) * WW + w0 + tx;
        out[o] = gv * tb[tx][rr] + x[o];
    }
}

// ---------------- launch ----------------
extern "C" void kernel_launch(void* const* d_in, const int* in_sizes, int n_in,
                              void* d_out, int out_size) {
    const float* x     = (const float*)d_in[0];
    const float* Wq    = (const float*)d_in[1];
    const float* bq    = (const float*)d_in[2];
    const float* Wk    = (const float*)d_in[3];
    const float* bk    = (const float*)d_in[4];
    const float* Wv    = (const float*)d_in[5];
    const float* bv    = (const float*)d_in[6];
    const float* gamma = (const float*)d_in[7];
    float* out = (float*)d_out;

    const int ASM = 44032 * 4;   // 176128 B
    cudaFuncSetAttribute(attn, cudaFuncAttributeMaxDynamicSharedMemorySize, ASM);

    pack_kernel<<<(CC * CC / 2 + 255) / 256, 256>>>(Wq, bq, Wk, bk, Wv, bv);
    qk_gemm<<<dim3(128, 4), 256>>>(x);
    v_gemm<<<dim3(4, 128, 4), 256>>>(x);
    transpose_qk<<<dim3(4, 4, BB * 128), dim3(32, 8, 1)>>>();
    transpose_v<<<dim3(2, 2, BB * CC), 256>>>();
    attn<<<1024, 512, ASM>>>();
    combine_kernel<<<dim3(WW / 32, CC / 64, BB * HH), dim3(32, 8, 1)>>>(x, gamma, out);
}